// round 10
// baseline (speedup 1.0000x reference)
#include <cuda_runtime.h>
#include <cuda_bf16.h>
#include <math_constants.h>
#include <cstdint>

// Problem shape: B=4, H=16, L=2048, D=64 (fp32)
#define BHN 64
#define LL  2048
#define DD  64

static const size_t CTX_ELEMS = (size_t)BHN * LL * DD;          // 8,388,608
static const size_t ATT_ELEMS = (size_t)BHN * LL * (size_t)LL;  // 268,435,456

// scratch (static __device__, allowed)
__device__ float g_inv[BHN * LL];                       // per-row 1/rowsum
__device__ float g_ctx_scratch[(size_t)BHN * LL * DD];  // ctx sink for attn-only

#if defined(__CUDA_ARCH_FEAT_SM103_ALL) || defined(__CUDA_ARCH_FEAT_SM100_ALL) || defined(__CUDA_ARCH_FEAT_SM101_ALL)
#define HAS_TC 1
#else
#define HAS_TC 0
#endif

// ===================== SMEM layouts =====================
// K1 (rowsum): [tmem][16 mbars][rowsum 256f][Q hi/lo 32K][Kbuf0 32K][Kbuf1 32K]
#define QK_TMEM 0
#define QK_MBAR 16
#define QK_RS   1024
#define QK_QH   2048
#define QK_QL   (QK_QH + 16384)
#define QK_KB0  34816
#define QK_KB1  67584
#define QK_SMEM 100352
// K2 (fused recompute+PV):
// [tmem][32 QK bars][32 PV bars][inv 512B] | Qh Ql | Kh Kl | Ph Pl | Vh Vl
#define F_TMEM 0
#define F_QKB  16
#define F_PVB  (F_QKB + 32 * 8)
#define F_INV  (F_PVB + 32 * 8)
#define F_QH   2048
#define F_QL   (F_QH + 16384)
#define F_KH   34816
#define F_KL   (F_KH + 8192)
#define F_PH   51200
#define F_PL   (F_PH + 16384)
#define F_VH   83968
#define F_VL   (F_VH + 8192)
#define F_SMEM 100352

#if HAS_TC
// ===================== PTX helpers =====================
__device__ __forceinline__ uint32_t smem_u32(const void* p) {
    uint32_t a;
    asm("{ .reg .u64 t; cvta.to.shared.u64 t, %1; cvt.u32.u64 %0, t; }" : "=r"(a) : "l"(p));
    return a;
}
__device__ __forceinline__ uint32_t elect_one() {
    uint32_t p;
    asm volatile("{\n\t.reg .pred p;\n\telect.sync _|p, 0xFFFFFFFF;\n\tselp.b32 %0, 1, 0, p;\n\t}" : "=r"(p));
    return p;
}
#define TC_ALLOC(sa, n)  asm volatile("tcgen05.alloc.cta_group::1.sync.aligned.shared::cta.b32 [%0], %1;" :: "r"(sa), "r"(n) : "memory")
#define TC_DEALLOC(t, n) asm volatile("tcgen05.dealloc.cta_group::1.sync.aligned.b32 %0, %1;" :: "r"(t), "r"(n))
#define TC_COMMIT(mb)    asm volatile("tcgen05.commit.cta_group::1.mbarrier::arrive::one.shared::cluster.b64 [%0];" :: "r"(mb) : "memory")
#define TC_WAIT_LD()     asm volatile("tcgen05.wait::ld.sync.aligned;" ::: "memory")
#define TC_FENCE_AFTER() asm volatile("tcgen05.fence::after_thread_sync;" ::: "memory")
#define TC_FENCE_BEFORE() asm volatile("tcgen05.fence::before_thread_sync;" ::: "memory")
#define FENCE_ASYNC()    asm volatile("fence.proxy.async.shared::cta;" ::: "memory")
#define MBAR_INIT(mb, c) asm volatile("mbarrier.init.shared.b64 [%0], %1;" :: "r"(mb), "r"(c) : "memory")
#define MBAR_INVAL(mb)   asm volatile("mbarrier.inval.shared.b64 [%0];" :: "r"(mb) : "memory")

#define MBAR_WAIT0(mb) do {                                                  \
    uint32_t _mb = (mb); uint32_t _done;                                     \
    asm volatile("{\n\t.reg .pred p;\n\t"                                    \
        "mbarrier.try_wait.parity.acquire.cta.shared::cta.b64 p, [%1], 0;\n\t" \
        "selp.b32 %0, 1, 0, p;\n\t}"                                         \
        : "=r"(_done) : "r"(_mb) : "memory");                                \
    if (!_done) {                                                            \
        asm volatile("{\n\t.reg .pred P1;\n\t"                               \
            "WL_%=:\n\t"                                                     \
            "mbarrier.try_wait.parity.acquire.cta.shared::cta.b64 P1, [%0], 0, 0x989680;\n\t" \
            "@P1 bra.uni WD_%=;\n\t"                                         \
            "bra.uni WL_%=;\n\t"                                             \
            "WD_%=:\n\t}"                                                    \
            :: "r"(_mb) : "memory");                                         \
    }                                                                        \
} while (0)

#define TC_LD_X32(r, ta) \
    asm volatile( \
        "tcgen05.ld.sync.aligned.32x32b.x32.b32 " \
        "{%0, %1, %2, %3, %4, %5, %6, %7, " \
        " %8, %9, %10, %11, %12, %13, %14, %15, " \
        " %16, %17, %18, %19, %20, %21, %22, %23, " \
        " %24, %25, %26, %27, %28, %29, %30, %31}, [%32];" \
        : "=r"((r)[0]),  "=r"((r)[1]),  "=r"((r)[2]),  "=r"((r)[3]), \
          "=r"((r)[4]),  "=r"((r)[5]),  "=r"((r)[6]),  "=r"((r)[7]), \
          "=r"((r)[8]),  "=r"((r)[9]),  "=r"((r)[10]), "=r"((r)[11]), \
          "=r"((r)[12]), "=r"((r)[13]), "=r"((r)[14]), "=r"((r)[15]), \
          "=r"((r)[16]), "=r"((r)[17]), "=r"((r)[18]), "=r"((r)[19]), \
          "=r"((r)[20]), "=r"((r)[21]), "=r"((r)[22]), "=r"((r)[23]), \
          "=r"((r)[24]), "=r"((r)[25]), "=r"((r)[26]), "=r"((r)[27]), \
          "=r"((r)[28]), "=r"((r)[29]), "=r"((r)[30]), "=r"((r)[31]) \
        : "r"(ta))

__device__ __forceinline__ void mma_f16_ss(uint32_t d, uint64_t ad, uint64_t bd,
                                           uint32_t idesc, uint32_t acc) {
    asm volatile(
        "{\n\t.reg .pred p;\n\tsetp.ne.u32 p, %4, 0;\n\t"
        "tcgen05.mma.cta_group::1.kind::f16 [%0], %1, %2, %3, {%5, %5, %5, %5}, p;\n\t}"
        :: "r"(d), "l"(ad), "l"(bd), "r"(idesc), "r"(acc), "r"(0u)
        : "memory");
}

__device__ __forceinline__ uint64_t make_desc(uint32_t addr) {
    return 0x4000404000010000ULL | (uint64_t)((addr >> 4) & 0x3FFF);
}
__device__ __forceinline__ int sw128(int off) { return off ^ ((off >> 3) & 0x70); }

// M=128, N=64 bf16->f32 (proven geometry)
#define IDESC_64 0x8100490u

__device__ __forceinline__ void split_sts4(char* hi_base, char* lo_base, int byte_off, float4 v) {
    int sw = sw128(byte_off);
    __nv_bfloat16 h0 = __float2bfloat16(v.x), h1 = __float2bfloat16(v.y),
                  h2 = __float2bfloat16(v.z), h3 = __float2bfloat16(v.w);
    float l0 = v.x - __bfloat162float(h0), l1 = v.y - __bfloat162float(h1),
          l2 = v.z - __bfloat162float(h2), l3 = v.w - __bfloat162float(h3);
    __nv_bfloat16 g0 = __float2bfloat16(l0), g1 = __float2bfloat16(l1),
                  g2 = __float2bfloat16(l2), g3 = __float2bfloat16(l3);
    uint2 hv, lv;
    hv.x = (uint32_t)__bfloat16_as_ushort(h0) | ((uint32_t)__bfloat16_as_ushort(h1) << 16);
    hv.y = (uint32_t)__bfloat16_as_ushort(h2) | ((uint32_t)__bfloat16_as_ushort(h3) << 16);
    lv.x = (uint32_t)__bfloat16_as_ushort(g0) | ((uint32_t)__bfloat16_as_ushort(g1) << 16);
    lv.y = (uint32_t)__bfloat16_as_ushort(g2) | ((uint32_t)__bfloat16_as_ushort(g3) << 16);
    *(uint2*)(hi_base + sw) = hv;
    *(uint2*)(lo_base + sw) = lv;
}
#endif  // HAS_TC

// ===================== K1: rowsums of exp(Q K^T) -> g_inv (no E store) ====
// grid (16, 64), 256 threads, pipelined (2 K smem bufs, 2 TMEM accumulators).
__global__ __launch_bounds__(256, 2) __cluster_dims__(1, 1, 1)
void qk_rowsum_tc(const float* __restrict__ Q, const float* __restrict__ K) {
    extern __shared__ char sm[];
    const int tid = threadIdx.x, wid = tid >> 5, lid = tid & 31;
    const int bh = blockIdx.y, tileM = blockIdx.x * 128;
    const float* Qb = Q + ((size_t)bh * LL + tileM) * DD;
    const float* Kb = K + (size_t)bh * LL * DD;

#if HAS_TC
    const uint32_t sbase = smem_u32(sm);
    const int wg = wid >> 2;
    const int myrow = (wid & 3) * 32 + lid;
    const int cbase = wg * 64;

    if (wid == 0) { TC_ALLOC(sbase + QK_TMEM, 256); }
    if (tid == 0) {
#pragma unroll
        for (int i = 0; i < 16; i++) MBAR_INIT(sbase + QK_MBAR + i * 8, 1);
    }
    __syncthreads();
    uint32_t tbase;
    asm volatile("ld.shared.b32 %0, [%1];" : "=r"(tbase) : "r"(sbase + QK_TMEM));

#pragma unroll
    for (int i = 0; i < 8; i++) {
        int lin = tid + i * 256;
        int row = lin >> 4, c4 = (lin & 15) << 2;
        float4 v = *(const float4*)(Qb + (size_t)row * DD + c4);
        split_sts4(sm + QK_QH, sm + QK_QL, row * 128 + c4 * 2, v);
    }
#pragma unroll
    for (int i = 0; i < 8; i++) {
        int lin = tid + i * 256;
        int row = lin >> 4, c4 = (lin & 15) << 2;
        float4 v = *(const float4*)(Kb + (size_t)row * DD + c4);
        split_sts4(sm + QK_KB0, sm + QK_KB0 + 16384, row * 128 + c4 * 2, v);
    }
    FENCE_ASYNC();
    __syncthreads();

    auto issue_qk = [&](uint32_t kbase, uint32_t dst, uint32_t bar) {
        uint64_t ah = make_desc(sbase + QK_QH), al = make_desc(sbase + QK_QL);
#pragma unroll
        for (int n = 0; n < 2; n++) {
            uint64_t bhd = make_desc(kbase + n * 8192);
            uint64_t bld = make_desc(kbase + 16384 + n * 8192);
            uint32_t d = dst + n * 64;
#pragma unroll
            for (int k = 0; k < 4; k++) mma_f16_ss(d, ah + k * 2, bhd + k * 2, IDESC_64, k > 0);
#pragma unroll
            for (int k = 0; k < 4; k++) mma_f16_ss(d, ah + k * 2, bld + k * 2, IDESC_64, 1);
#pragma unroll
            for (int k = 0; k < 4; k++) mma_f16_ss(d, al + k * 2, bhd + k * 2, IDESC_64, 1);
        }
        TC_COMMIT(bar);
    };

    if (wid == 0 && elect_one()) issue_qk(sbase + QK_KB0, tbase, sbase + QK_MBAR);

    float rs = 0.f;
    for (int nt = 0; nt < 16; nt++) {
        if (nt < 15) {
            const float* Kt = Kb + (size_t)(nt + 1) * 128 * DD;
            uint32_t kb = ((nt + 1) & 1) ? QK_KB1 : QK_KB0;
#pragma unroll
            for (int i = 0; i < 8; i++) {
                int lin = tid + i * 256;
                int row = lin >> 4, c4 = (lin & 15) << 2;
                float4 v = *(const float4*)(Kt + (size_t)row * DD + c4);
                split_sts4(sm + kb, sm + kb + 16384, row * 128 + c4 * 2, v);
            }
            FENCE_ASYNC();
        }
        __syncthreads();
        if (nt < 15 && wid == 0 && elect_one()) {
            uint32_t kb = ((nt + 1) & 1) ? QK_KB1 : QK_KB0;
            issue_qk(sbase + kb, tbase + ((nt + 1) & 1) * 128, sbase + QK_MBAR + (nt + 1) * 8);
        }
        MBAR_WAIT0(sbase + QK_MBAR + nt * 8);
        TC_FENCE_AFTER();

        const uint32_t tb = tbase + (nt & 1) * 128 + cbase;
#pragma unroll
        for (int c0 = 0; c0 < 64; c0 += 32) {
            uint32_t r[32];
            TC_LD_X32(r, tb + c0);
            TC_WAIT_LD();
#pragma unroll
            for (int j = 0; j < 32; j++) rs += __expf(__uint_as_float(r[j]));
        }
        TC_FENCE_BEFORE();
    }

    float* rsbuf = (float*)(sm + QK_RS);
    rsbuf[wg * 128 + myrow] = rs;
    __syncthreads();
    if (wg == 0) g_inv[bh * LL + tileM + myrow] = 1.0f / (rsbuf[myrow] + rsbuf[128 + myrow]);

    __syncthreads();
    if (tid == 0) {
#pragma unroll
        for (int i = 0; i < 16; i++) MBAR_INVAL(sbase + QK_MBAR + i * 8);
    }
    __syncthreads();
    if (wid == 0) { TC_DEALLOC(tbase, 256); }

#else  // scalar fallback
    float* Ts = (float*)sm;
    float q[DD];
    if (tid < 128) {
#pragma unroll
        for (int d = 0; d < DD; d++) q[d] = Qb[(size_t)tid * DD + d];
    }
    float rs = 0.f;
    for (int nt = 0; nt < 16; nt++) {
        for (int lin = tid; lin < 128 * 16; lin += blockDim.x) {
            int row = lin >> 4, c4 = (lin & 15) << 2;
            *(float4*)(Ts + row * DD + c4) =
                *(const float4*)(Kb + (size_t)(nt * 128 + row) * DD + c4);
        }
        __syncthreads();
        if (tid < 128) {
            for (int j = 0; j < 128; j++) {
                float s = 0.f;
#pragma unroll
                for (int d = 0; d < DD; d++) s = fmaf(q[d], Ts[j * DD + d], s);
                rs += __expf(s);
            }
        }
        __syncthreads();
    }
    if (tid < 128) g_inv[bh * LL + tileM + tid] = 1.0f / rs;
#endif
}

// ========== K2: recompute QK, write normalized attn once, PV accumulate ====
// grid (16, 64), 256 threads. 32 iterations of 64-row K-half-tiles.
__global__ __launch_bounds__(256, 2) __cluster_dims__(1, 1, 1)
void fused_pv_tc(const float* __restrict__ Q, const float* __restrict__ K,
                 const float* __restrict__ V, float* __restrict__ att,
                 float* __restrict__ ctx) {
    extern __shared__ char sm[];
    const int tid = threadIdx.x, wid = tid >> 5, lid = tid & 31;
    const int bh = blockIdx.y, tileM = blockIdx.x * 128;
    const float* Qb = Q + ((size_t)bh * LL + tileM) * DD;
    const float* Kb = K + (size_t)bh * LL * DD;
    const float* Vb = V + (size_t)bh * LL * DD;
    float* Eb = att + ((size_t)bh * LL + tileM) * LL;
    float* Ob = ctx + ((size_t)bh * LL + tileM) * DD;

#if HAS_TC
    const uint32_t sbase = smem_u32(sm);
    const int wg = wid >> 2;                 // 0: cols 0-31, 1: cols 32-63 of S
    const int myrow = (wid & 3) * 32 + lid;

    if (wid == 0) { TC_ALLOC(sbase + F_TMEM, 256); }
    if (tid == 0) {
#pragma unroll
        for (int i = 0; i < 32; i++) { MBAR_INIT(sbase + F_QKB + i * 8, 1); MBAR_INIT(sbase + F_PVB + i * 8, 1); }
    }
    float* invS = (float*)(sm + F_INV);
    if (tid < 128) invS[tid] = g_inv[bh * LL + tileM + tid];
    __syncthreads();
    uint32_t tbase;
    asm volatile("ld.shared.b32 %0, [%1];" : "=r"(tbase) : "r"(sbase + F_TMEM));
    const uint32_t T_S = tbase;          // Sbuf0 @ +0, Sbuf1 @ +64
    const uint32_t T_O = tbase + 128;    // O accumulator, 64 cols

    // resident Q tile
#pragma unroll
    for (int i = 0; i < 8; i++) {
        int lin = tid + i * 256;
        int row = lin >> 4, c4 = (lin & 15) << 2;
        float4 v = *(const float4*)(Qb + (size_t)row * DD + c4);
        split_sts4(sm + F_QH, sm + F_QL, row * 128 + c4 * 2, v);
    }
    // K half-tile 0 (rows 0..63)
#pragma unroll
    for (int i = 0; i < 4; i++) {
        int lin = tid + i * 256;
        int row = lin >> 4, c4 = (lin & 15) << 2;
        float4 v = *(const float4*)(Kb + (size_t)row * DD + c4);
        split_sts4(sm + F_KH, sm + F_KL, row * 128 + c4 * 2, v);
    }
    FENCE_ASYNC();
    __syncthreads();

    auto issue_qk = [&](uint32_t dst, uint32_t bar) {
        uint64_t ah = make_desc(sbase + F_QH), al = make_desc(sbase + F_QL);
        uint64_t bhd = make_desc(sbase + F_KH), bld = make_desc(sbase + F_KL);
#pragma unroll
        for (int k = 0; k < 4; k++) mma_f16_ss(dst, ah + k * 2, bhd + k * 2, IDESC_64, k > 0);
#pragma unroll
        for (int k = 0; k < 4; k++) mma_f16_ss(dst, ah + k * 2, bld + k * 2, IDESC_64, 1);
#pragma unroll
        for (int k = 0; k < 4; k++) mma_f16_ss(dst, al + k * 2, bhd + k * 2, IDESC_64, 1);
        TC_COMMIT(bar);
    };
    auto issue_pv = [&](int first, uint32_t bar) {
        uint64_t ah = make_desc(sbase + F_PH), al = make_desc(sbase + F_PL);
        uint64_t bhd = make_desc(sbase + F_VH), bld = make_desc(sbase + F_VL);
#pragma unroll
        for (int k = 0; k < 4; k++) mma_f16_ss(T_O, ah + k * 2, bhd + k * 2, IDESC_64, !(first && k == 0));
#pragma unroll
        for (int k = 0; k < 4; k++) mma_f16_ss(T_O, ah + k * 2, bld + k * 2, IDESC_64, 1);
#pragma unroll
        for (int k = 0; k < 4; k++) mma_f16_ss(T_O, al + k * 2, bhd + k * 2, IDESC_64, 1);
        TC_COMMIT(bar);
    };

    if (wid == 0 && elect_one()) issue_qk(T_S, sbase + F_QKB);

    for (int it = 0; it < 32; it++) {
        const int k0 = it * 64;
        MBAR_WAIT0(sbase + F_QKB + it * 8);
        TC_FENCE_AFTER();
        if (it >= 1) MBAR_WAIT0(sbase + F_PVB + (it - 1) * 8);

        // K half-tile it+1 (QK(it) done reading the single K buffer)
        if (it < 31) {
            const float* Kt = Kb + (size_t)(k0 + 64) * DD;
#pragma unroll
            for (int i = 0; i < 4; i++) {
                int lin = tid + i * 256;
                int row = lin >> 4, c4 = (lin & 15) << 2;
                float4 v = *(const float4*)(Kt + (size_t)row * DD + c4);
                split_sts4(sm + F_KH, sm + F_KL, row * 128 + c4 * 2, v);
            }
        }
        // V half-tile it: rows k0..k0+63, transposed [n][k] (PV(it-1) done)
#pragma unroll
        for (int i = 0; i < 4; i++) {
            int lin = tid + i * 256;
            int kr = lin >> 4, n4 = (lin & 15) << 2;
            float4 v = *(const float4*)(Vb + (size_t)(k0 + kr) * DD + n4);
            float vv[4] = {v.x, v.y, v.z, v.w};
#pragma unroll
            for (int j = 0; j < 4; j++) {
                int sw = sw128((n4 + j) * 128 + kr * 2);
                __nv_bfloat16 hh = __float2bfloat16(vv[j]);
                float lo = vv[j] - __bfloat162float(hh);
                *(__nv_bfloat16*)(sm + F_VH + sw) = hh;
                *(__nv_bfloat16*)(sm + F_VL + sw) = __float2bfloat16(lo);
            }
        }
        FENCE_ASYNC();
        __syncthreads();
        if (it < 31 && wid == 0 && elect_one())
            issue_qk(T_S + ((it + 1) & 1) * 64, sbase + F_QKB + (it + 1) * 8);

        // epilogue: S(it) -> exp * inv -> attn (single write) + split into P
        {
            const float iv = invS[myrow];
            uint32_t r[32];
            TC_LD_X32(r, T_S + (it & 1) * 64 + wg * 32);
            TC_WAIT_LD();
            float e[32];
#pragma unroll
            for (int j = 0; j < 32; j++) e[j] = __expf(__uint_as_float(r[j])) * iv;
            float* erow = Eb + (size_t)myrow * LL + k0 + wg * 32;
#pragma unroll
            for (int q = 0; q < 8; q++)
                *(float4*)(erow + q * 4) =
                    make_float4(e[q * 4], e[q * 4 + 1], e[q * 4 + 2], e[q * 4 + 3]);
#pragma unroll
            for (int q = 0; q < 8; q++)
                split_sts4(sm + F_PH, sm + F_PL, myrow * 128 + (wg * 32 + q * 4) * 2,
                           make_float4(e[q * 4], e[q * 4 + 1], e[q * 4 + 2], e[q * 4 + 3]));
        }
        TC_FENCE_BEFORE();
        FENCE_ASYNC();
        __syncthreads();
        if (wid == 0 && elect_one()) issue_pv(it == 0, sbase + F_PVB + it * 8);
    }

    MBAR_WAIT0(sbase + F_PVB + 31 * 8);
    TC_FENCE_AFTER();
    {
        uint32_t r[32];
        TC_LD_X32(r, T_O + wg * 32);
        TC_WAIT_LD();
        TC_FENCE_BEFORE();
        float* orow = Ob + (size_t)myrow * DD + wg * 32;
#pragma unroll
        for (int q = 0; q < 8; q++)
            *(float4*)(orow + q * 4) = make_float4(__uint_as_float(r[q * 4]),
                                                   __uint_as_float(r[q * 4 + 1]),
                                                   __uint_as_float(r[q * 4 + 2]),
                                                   __uint_as_float(r[q * 4 + 3]));
    }
    __syncthreads();
    if (tid == 0) {
#pragma unroll
        for (int i = 0; i < 32; i++) { MBAR_INVAL(sbase + F_QKB + i * 8); MBAR_INVAL(sbase + F_PVB + i * 8); }
    }
    __syncthreads();
    if (wid == 0) { TC_DEALLOC(tbase, 256); }

#else  // scalar fallback
    float* Ts = (float*)sm;
    float q[DD], acc[DD];
    float iv = 0.f;
    if (tid < 128) {
#pragma unroll
        for (int d = 0; d < DD; d++) { q[d] = Qb[(size_t)tid * DD + d]; acc[d] = 0.f; }
        iv = g_inv[bh * LL + tileM + tid];
    }
    float* erow = Eb + (size_t)tid * LL;
    for (int nt = 0; nt < 16; nt++) {
        for (int lin = tid; lin < 128 * 16; lin += blockDim.x) {
            int row = lin >> 4, c4 = (lin & 15) << 2;
            *(float4*)(Ts + row * DD + c4) =
                *(const float4*)(Kb + (size_t)(nt * 128 + row) * DD + c4);
        }
        __syncthreads();
        float p[128];
        if (tid < 128) {
            for (int j = 0; j < 128; j++) {
                float s = 0.f;
#pragma unroll
                for (int d = 0; d < DD; d++) s = fmaf(q[d], Ts[j * DD + d], s);
                p[j] = __expf(s) * iv;
                erow[nt * 128 + j] = p[j];
            }
        }
        __syncthreads();
        for (int lin = tid; lin < 128 * 16; lin += blockDim.x) {
            int row = lin >> 4, c4 = (lin & 15) << 2;
            *(float4*)(Ts + row * DD + c4) =
                *(const float4*)(Vb + (size_t)(nt * 128 + row) * DD + c4);
        }
        __syncthreads();
        if (tid < 128) {
            for (int j = 0; j < 128; j++)
#pragma unroll
                for (int d = 0; d < DD; d++) acc[d] = fmaf(p[j], Ts[j * DD + d], acc[d]);
        }
        __syncthreads();
    }
    if (tid < 128) {
#pragma unroll
        for (int d = 0; d < DD; d += 4)
            *(float4*)(Ob + (size_t)tid * DD + d) =
                make_float4(acc[d], acc[d + 1], acc[d + 2], acc[d + 3]);
    }
#endif
}

// ---------------------------------------------------------------------------
// ctx-only fallback: fused per-row attention (rarely used branch).
// ---------------------------------------------------------------------------
__global__ __launch_bounds__(256) void fused_ctx_kernel(const float* __restrict__ Q,
                                                        const float* __restrict__ K,
                                                        const float* __restrict__ V,
                                                        float* __restrict__ O) {
    __shared__ float q[DD];
    __shared__ float s[LL];
    __shared__ float wred[8];
    __shared__ float bcast;

    const int bh = blockIdx.y;
    const int qi = blockIdx.x;
    const float* Qb = Q + ((size_t)bh * LL + qi) * DD;
    const float* Kb = K + (size_t)bh * LL * DD;
    const float* Vb = V + (size_t)bh * LL * DD;
    float* Ob = O + ((size_t)bh * LL + qi) * DD;

    const int tid = threadIdx.x;
    const int warp = tid >> 5, lane = tid & 31;
    if (tid < DD) q[tid] = Qb[tid];
    __syncthreads();

    float m = -CUDART_INF_F;
    for (int j = tid; j < LL; j += 256) {
        float d = 0.f;
#pragma unroll
        for (int d0 = 0; d0 < DD; d0++) d = fmaf(q[d0], Kb[(size_t)j * DD + d0], d);
        s[j] = d;
        m = fmaxf(m, d);
    }
#pragma unroll
    for (int o = 16; o > 0; o >>= 1) m = fmaxf(m, __shfl_xor_sync(0xffffffffu, m, o));
    if (lane == 0) wred[warp] = m;
    __syncthreads();
    if (warp == 0) {
        float x = (lane < 8) ? wred[lane] : -CUDART_INF_F;
#pragma unroll
        for (int o = 4; o > 0; o >>= 1) x = fmaxf(x, __shfl_xor_sync(0xffffffffu, x, o));
        if (lane == 0) bcast = x;
    }
    __syncthreads();
    m = bcast;

    float ssum = 0.f;
    for (int j = tid; j < LL; j += 256) {
        float e = __expf(s[j] - m);
        s[j] = e;
        ssum += e;
    }
#pragma unroll
    for (int o = 16; o > 0; o >>= 1) ssum += __shfl_xor_sync(0xffffffffu, ssum, o);
    __syncthreads();
    if (lane == 0) wred[warp] = ssum;
    __syncthreads();
    if (warp == 0) {
        float x = (lane < 8) ? wred[lane] : 0.f;
#pragma unroll
        for (int o = 4; o > 0; o >>= 1) x += __shfl_xor_sync(0xffffffffu, x, o);
        if (lane == 0) bcast = 1.f / x;
    }
    __syncthreads();
    const float inv = bcast;

    if (tid < DD) {
        float a = 0.f;
        for (int j = 0; j < LL; j++) a = fmaf(s[j], Vb[(size_t)j * DD + tid], a);
        Ob[tid] = a * inv;
    }
}

// ---------------------------------------------------------------------------
extern "C" void kernel_launch(void* const* d_in, const int* in_sizes, int n_in,
                              void* d_out, int out_size) {
    const float* Q = (const float*)d_in[0];
    const float* K = (const float*)d_in[1];
    const float* V = (const float*)d_in[2];
    float* out = (float*)d_out;

    cudaFuncSetAttribute(qk_rowsum_tc, cudaFuncAttributeMaxDynamicSharedMemorySize, QK_SMEM);
    cudaFuncSetAttribute(fused_pv_tc, cudaFuncAttributeMaxDynamicSharedMemorySize, F_SMEM);

    if ((size_t)out_size >= CTX_ELEMS + ATT_ELEMS) {
        float* ctx = out;
        float* att = out + CTX_ELEMS;
        qk_rowsum_tc<<<dim3(16, BHN), 256, QK_SMEM>>>(Q, K);
        fused_pv_tc<<<dim3(16, BHN), 256, F_SMEM>>>(Q, K, V, att, ctx);
    } else if ((size_t)out_size == ATT_ELEMS) {
        float* scratch = nullptr;
        cudaGetSymbolAddress((void**)&scratch, g_ctx_scratch);
        qk_rowsum_tc<<<dim3(16, BHN), 256, QK_SMEM>>>(Q, K);
        fused_pv_tc<<<dim3(16, BHN), 256, F_SMEM>>>(Q, K, V, out, scratch);
    } else {
        fused_ctx_kernel<<<dim3(LL, BHN), 256>>>(Q, K, V, out);
    }
}

// round 12
// speedup vs baseline: 1.5294x; 1.5294x over previous
#include <cuda_runtime.h>
#include <cuda_bf16.h>
#include <math_constants.h>
#include <cstdint>

// Problem shape: B=4, H=16, L=2048, D=64 (fp32)
#define BHN 64
#define LL  2048
#define DD  64

static const size_t CTX_ELEMS = (size_t)BHN * LL * DD;          // 8,388,608
static const size_t ATT_ELEMS = (size_t)BHN * LL * (size_t)LL;  // 268,435,456

// scratch (static __device__, allowed)
__device__ float g_inv[BHN * LL];                       // per-row 1/rowsum
__device__ float g_ctx_scratch[(size_t)BHN * LL * DD];  // ctx sink for attn-only

#if defined(__CUDA_ARCH_FEAT_SM103_ALL) || defined(__CUDA_ARCH_FEAT_SM100_ALL) || defined(__CUDA_ARCH_FEAT_SM101_ALL)
#define HAS_TC 1
#else
#define HAS_TC 0
#endif

// ===================== SMEM layouts =====================
// K1 (rowsum): [tmem][16 mbars][rowsum 512f][Q hi/lo 32K][Kbuf0 32K][Kbuf1 32K]
#define QK_TMEM 0
#define QK_MBAR 16
#define QK_RS   1024                      /* 512 floats = 2048 B */
#define QK_QH   4096
#define QK_QL   (QK_QH + 16384)
#define QK_KB0  36864
#define QK_KB1  69632
#define QK_SMEM 102400
// K2 (fused recompute+PV):
// [tmem][32 QK bars][32 PV bars][inv 512B] | Qh Ql | Kh Kl | Ph Pl | Vh Vl
#define F_TMEM 0
#define F_QKB  16
#define F_PVB  (F_QKB + 32 * 8)
#define F_INV  (F_PVB + 32 * 8)
#define F_QH   2048
#define F_QL   (F_QH + 16384)
#define F_KH   34816
#define F_KL   (F_KH + 8192)
#define F_PH   51200
#define F_PL   (F_PH + 16384)
#define F_VH   83968
#define F_VL   (F_VH + 8192)
#define F_SMEM 100352

#if HAS_TC
// ===================== PTX helpers =====================
__device__ __forceinline__ uint32_t smem_u32(const void* p) {
    uint32_t a;
    asm("{ .reg .u64 t; cvta.to.shared.u64 t, %1; cvt.u32.u64 %0, t; }" : "=r"(a) : "l"(p));
    return a;
}
__device__ __forceinline__ uint32_t elect_one() {
    uint32_t p;
    asm volatile("{\n\t.reg .pred p;\n\telect.sync _|p, 0xFFFFFFFF;\n\tselp.b32 %0, 1, 0, p;\n\t}" : "=r"(p));
    return p;
}
#define TC_ALLOC(sa, n)  asm volatile("tcgen05.alloc.cta_group::1.sync.aligned.shared::cta.b32 [%0], %1;" :: "r"(sa), "r"(n) : "memory")
#define TC_DEALLOC(t, n) asm volatile("tcgen05.dealloc.cta_group::1.sync.aligned.b32 %0, %1;" :: "r"(t), "r"(n))
#define TC_COMMIT(mb)    asm volatile("tcgen05.commit.cta_group::1.mbarrier::arrive::one.shared::cluster.b64 [%0];" :: "r"(mb) : "memory")
#define TC_WAIT_LD()     asm volatile("tcgen05.wait::ld.sync.aligned;" ::: "memory")
#define TC_FENCE_AFTER() asm volatile("tcgen05.fence::after_thread_sync;" ::: "memory")
#define TC_FENCE_BEFORE() asm volatile("tcgen05.fence::before_thread_sync;" ::: "memory")
#define FENCE_ASYNC()    asm volatile("fence.proxy.async.shared::cta;" ::: "memory")
#define MBAR_INIT(mb, c) asm volatile("mbarrier.init.shared.b64 [%0], %1;" :: "r"(mb), "r"(c) : "memory")
#define MBAR_INVAL(mb)   asm volatile("mbarrier.inval.shared.b64 [%0];" :: "r"(mb) : "memory")

#define MBAR_WAIT0(mb) do {                                                  \
    uint32_t _mb = (mb); uint32_t _done;                                     \
    asm volatile("{\n\t.reg .pred p;\n\t"                                    \
        "mbarrier.try_wait.parity.acquire.cta.shared::cta.b64 p, [%1], 0;\n\t" \
        "selp.b32 %0, 1, 0, p;\n\t}"                                         \
        : "=r"(_done) : "r"(_mb) : "memory");                                \
    if (!_done) {                                                            \
        asm volatile("{\n\t.reg .pred P1;\n\t"                               \
            "WL_%=:\n\t"                                                     \
            "mbarrier.try_wait.parity.acquire.cta.shared::cta.b64 P1, [%0], 0, 0x989680;\n\t" \
            "@P1 bra.uni WD_%=;\n\t"                                         \
            "bra.uni WL_%=;\n\t"                                             \
            "WD_%=:\n\t}"                                                    \
            :: "r"(_mb) : "memory");                                         \
    }                                                                        \
} while (0)

#define TC_LD_X32(r, ta) \
    asm volatile( \
        "tcgen05.ld.sync.aligned.32x32b.x32.b32 " \
        "{%0, %1, %2, %3, %4, %5, %6, %7, " \
        " %8, %9, %10, %11, %12, %13, %14, %15, " \
        " %16, %17, %18, %19, %20, %21, %22, %23, " \
        " %24, %25, %26, %27, %28, %29, %30, %31}, [%32];" \
        : "=r"((r)[0]),  "=r"((r)[1]),  "=r"((r)[2]),  "=r"((r)[3]), \
          "=r"((r)[4]),  "=r"((r)[5]),  "=r"((r)[6]),  "=r"((r)[7]), \
          "=r"((r)[8]),  "=r"((r)[9]),  "=r"((r)[10]), "=r"((r)[11]), \
          "=r"((r)[12]), "=r"((r)[13]), "=r"((r)[14]), "=r"((r)[15]), \
          "=r"((r)[16]), "=r"((r)[17]), "=r"((r)[18]), "=r"((r)[19]), \
          "=r"((r)[20]), "=r"((r)[21]), "=r"((r)[22]), "=r"((r)[23]), \
          "=r"((r)[24]), "=r"((r)[25]), "=r"((r)[26]), "=r"((r)[27]), \
          "=r"((r)[28]), "=r"((r)[29]), "=r"((r)[30]), "=r"((r)[31]) \
        : "r"(ta))

#define TC_LD_X16(r, ta) \
    asm volatile( \
        "tcgen05.ld.sync.aligned.32x32b.x16.b32 " \
        "{%0, %1, %2, %3, %4, %5, %6, %7, " \
        " %8, %9, %10, %11, %12, %13, %14, %15}, [%16];" \
        : "=r"((r)[0]),  "=r"((r)[1]),  "=r"((r)[2]),  "=r"((r)[3]), \
          "=r"((r)[4]),  "=r"((r)[5]),  "=r"((r)[6]),  "=r"((r)[7]), \
          "=r"((r)[8]),  "=r"((r)[9]),  "=r"((r)[10]), "=r"((r)[11]), \
          "=r"((r)[12]), "=r"((r)[13]), "=r"((r)[14]), "=r"((r)[15]) \
        : "r"(ta))

__device__ __forceinline__ void mma_f16_ss(uint32_t d, uint64_t ad, uint64_t bd,
                                           uint32_t idesc, uint32_t acc) {
    asm volatile(
        "{\n\t.reg .pred p;\n\tsetp.ne.u32 p, %4, 0;\n\t"
        "tcgen05.mma.cta_group::1.kind::f16 [%0], %1, %2, %3, {%5, %5, %5, %5}, p;\n\t}"
        :: "r"(d), "l"(ad), "l"(bd), "r"(idesc), "r"(acc), "r"(0u)
        : "memory");
}

__device__ __forceinline__ uint64_t make_desc(uint32_t addr) {
    return 0x4000404000010000ULL | (uint64_t)((addr >> 4) & 0x3FFF);
}
__device__ __forceinline__ int sw128(int off) { return off ^ ((off >> 3) & 0x70); }

// M=128, N=64 bf16->f32 (proven geometry)
#define IDESC_64 0x8100490u

__device__ __forceinline__ void split_sts4(char* hi_base, char* lo_base, int byte_off, float4 v) {
    int sw = sw128(byte_off);
    __nv_bfloat16 h0 = __float2bfloat16(v.x), h1 = __float2bfloat16(v.y),
                  h2 = __float2bfloat16(v.z), h3 = __float2bfloat16(v.w);
    float l0 = v.x - __bfloat162float(h0), l1 = v.y - __bfloat162float(h1),
          l2 = v.z - __bfloat162float(h2), l3 = v.w - __bfloat162float(h3);
    __nv_bfloat16 g0 = __float2bfloat16(l0), g1 = __float2bfloat16(l1),
                  g2 = __float2bfloat16(l2), g3 = __float2bfloat16(l3);
    uint2 hv, lv;
    hv.x = (uint32_t)__bfloat16_as_ushort(h0) | ((uint32_t)__bfloat16_as_ushort(h1) << 16);
    hv.y = (uint32_t)__bfloat16_as_ushort(h2) | ((uint32_t)__bfloat16_as_ushort(h3) << 16);
    lv.x = (uint32_t)__bfloat16_as_ushort(g0) | ((uint32_t)__bfloat16_as_ushort(g1) << 16);
    lv.y = (uint32_t)__bfloat16_as_ushort(g2) | ((uint32_t)__bfloat16_as_ushort(g3) << 16);
    *(uint2*)(hi_base + sw) = hv;
    *(uint2*)(lo_base + sw) = lv;
}
#endif  // HAS_TC

// ===================== K1: rowsums of exp(Q K^T) -> g_inv (no E store) ====
// grid (16, 64), 512 threads, pipelined (2 K smem bufs, 2 TMEM accumulators).
__global__ __launch_bounds__(512, 1) __cluster_dims__(1, 1, 1)
void qk_rowsum_tc(const float* __restrict__ Q, const float* __restrict__ K) {
    extern __shared__ char sm[];
    const int tid = threadIdx.x, wid = tid >> 5, lid = tid & 31;
    const int bh = blockIdx.y, tileM = blockIdx.x * 128;
    const float* Qb = Q + ((size_t)bh * LL + tileM) * DD;
    const float* Kb = K + (size_t)bh * LL * DD;

#if HAS_TC
    const uint32_t sbase = smem_u32(sm);
    const int wg = wid >> 2;                 // 0..3 -> cols wg*32..wg*32+31
    const int myrow = (wid & 3) * 32 + lid;

    if (wid == 0) { TC_ALLOC(sbase + QK_TMEM, 256); }
    if (tid == 0) {
#pragma unroll
        for (int i = 0; i < 16; i++) MBAR_INIT(sbase + QK_MBAR + i * 8, 1);
    }
    __syncthreads();
    uint32_t tbase;
    asm volatile("ld.shared.b32 %0, [%1];" : "=r"(tbase) : "r"(sbase + QK_TMEM));

#pragma unroll
    for (int i = 0; i < 4; i++) {
        int lin = tid + i * 512;
        int row = lin >> 4, c4 = (lin & 15) << 2;
        float4 v = *(const float4*)(Qb + (size_t)row * DD + c4);
        split_sts4(sm + QK_QH, sm + QK_QL, row * 128 + c4 * 2, v);
    }
#pragma unroll
    for (int i = 0; i < 4; i++) {
        int lin = tid + i * 512;
        int row = lin >> 4, c4 = (lin & 15) << 2;
        float4 v = *(const float4*)(Kb + (size_t)row * DD + c4);
        split_sts4(sm + QK_KB0, sm + QK_KB0 + 16384, row * 128 + c4 * 2, v);
    }
    FENCE_ASYNC();
    __syncthreads();

    auto issue_qk = [&](uint32_t kbase, uint32_t dst, uint32_t bar) {
        uint64_t ah = make_desc(sbase + QK_QH), al = make_desc(sbase + QK_QL);
#pragma unroll
        for (int n = 0; n < 2; n++) {
            uint64_t bhd = make_desc(kbase + n * 8192);
            uint64_t bld = make_desc(kbase + 16384 + n * 8192);
            uint32_t d = dst + n * 64;
#pragma unroll
            for (int k = 0; k < 4; k++) mma_f16_ss(d, ah + k * 2, bhd + k * 2, IDESC_64, k > 0);
#pragma unroll
            for (int k = 0; k < 4; k++) mma_f16_ss(d, ah + k * 2, bld + k * 2, IDESC_64, 1);
#pragma unroll
            for (int k = 0; k < 4; k++) mma_f16_ss(d, al + k * 2, bhd + k * 2, IDESC_64, 1);
        }
        TC_COMMIT(bar);
    };

    if (wid == 0 && elect_one()) issue_qk(sbase + QK_KB0, tbase, sbase + QK_MBAR);

    float rs = 0.f;
    for (int nt = 0; nt < 16; nt++) {
        if (nt < 15) {
            const float* Kt = Kb + (size_t)(nt + 1) * 128 * DD;
            uint32_t kb = ((nt + 1) & 1) ? QK_KB1 : QK_KB0;
#pragma unroll
            for (int i = 0; i < 4; i++) {
                int lin = tid + i * 512;
                int row = lin >> 4, c4 = (lin & 15) << 2;
                float4 v = *(const float4*)(Kt + (size_t)row * DD + c4);
                split_sts4(sm + kb, sm + kb + 16384, row * 128 + c4 * 2, v);
            }
            FENCE_ASYNC();
        }
        __syncthreads();
        if (nt < 15 && wid == 0 && elect_one()) {
            uint32_t kb = ((nt + 1) & 1) ? QK_KB1 : QK_KB0;
            issue_qk(sbase + kb, tbase + ((nt + 1) & 1) * 128, sbase + QK_MBAR + (nt + 1) * 8);
        }
        MBAR_WAIT0(sbase + QK_MBAR + nt * 8);
        TC_FENCE_AFTER();

        // 4 warp-groups x 32 cols each
        {
            uint32_t r[32];
            TC_LD_X32(r, tbase + (nt & 1) * 128 + wg * 32);
            TC_WAIT_LD();
#pragma unroll
            for (int j = 0; j < 32; j++) rs += __expf(__uint_as_float(r[j]));
        }
        TC_FENCE_BEFORE();
    }

    float* rsbuf = (float*)(sm + QK_RS);
    rsbuf[wg * 128 + myrow] = rs;
    __syncthreads();
    if (wg == 0)
        g_inv[bh * LL + tileM + myrow] =
            1.0f / (rsbuf[myrow] + rsbuf[128 + myrow] + rsbuf[256 + myrow] + rsbuf[384 + myrow]);

    __syncthreads();
    if (tid == 0) {
#pragma unroll
        for (int i = 0; i < 16; i++) MBAR_INVAL(sbase + QK_MBAR + i * 8);
    }
    __syncthreads();
    if (wid == 0) { TC_DEALLOC(tbase, 256); }

#else  // scalar fallback
    float* Ts = (float*)sm;
    float q[DD];
    if (tid < 128) {
#pragma unroll
        for (int d = 0; d < DD; d++) q[d] = Qb[(size_t)tid * DD + d];
    }
    float rs = 0.f;
    for (int nt = 0; nt < 16; nt++) {
        for (int lin = tid; lin < 128 * 16; lin += blockDim.x) {
            int row = lin >> 4, c4 = (lin & 15) << 2;
            *(float4*)(Ts + row * DD + c4) =
                *(const float4*)(Kb + (size_t)(nt * 128 + row) * DD + c4);
        }
        __syncthreads();
        if (tid < 128) {
            for (int j = 0; j < 128; j++) {
                float s = 0.f;
#pragma unroll
                for (int d = 0; d < DD; d++) s = fmaf(q[d], Ts[j * DD + d], s);
                rs += __expf(s);
            }
        }
        __syncthreads();
    }
    if (tid < 128) g_inv[bh * LL + tileM + tid] = 1.0f / rs;
#endif
}

// ========== K2: recompute QK, write normalized attn once, PV accumulate ====
// grid (16, 64), 512 threads. 32 iterations of 64-row K-half-tiles.
__global__ __launch_bounds__(512, 1) __cluster_dims__(1, 1, 1)
void fused_pv_tc(const float* __restrict__ Q, const float* __restrict__ K,
                 const float* __restrict__ V, float* __restrict__ att,
                 float* __restrict__ ctx) {
    extern __shared__ char sm[];
    const int tid = threadIdx.x, wid = tid >> 5, lid = tid & 31;
    const int bh = blockIdx.y, tileM = blockIdx.x * 128;
    const float* Qb = Q + ((size_t)bh * LL + tileM) * DD;
    const float* Kb = K + (size_t)bh * LL * DD;
    const float* Vb = V + (size_t)bh * LL * DD;
    float* Eb = att + ((size_t)bh * LL + tileM) * LL;
    float* Ob = ctx + ((size_t)bh * LL + tileM) * DD;

#if HAS_TC
    const uint32_t sbase = smem_u32(sm);
    const int wg = wid >> 2;                 // 0..3 -> cols wg*16..wg*16+15
    const int myrow = (wid & 3) * 32 + lid;

    if (wid == 0) { TC_ALLOC(sbase + F_TMEM, 256); }
    if (tid == 0) {
#pragma unroll
        for (int i = 0; i < 32; i++) { MBAR_INIT(sbase + F_QKB + i * 8, 1); MBAR_INIT(sbase + F_PVB + i * 8, 1); }
    }
    float* invS = (float*)(sm + F_INV);
    if (tid < 128) invS[tid] = g_inv[bh * LL + tileM + tid];
    __syncthreads();
    uint32_t tbase;
    asm volatile("ld.shared.b32 %0, [%1];" : "=r"(tbase) : "r"(sbase + F_TMEM));
    const uint32_t T_S = tbase;          // Sbuf0 @ +0, Sbuf1 @ +64
    const uint32_t T_O = tbase + 128;    // O accumulator, 64 cols

    // resident Q tile
#pragma unroll
    for (int i = 0; i < 4; i++) {
        int lin = tid + i * 512;
        int row = lin >> 4, c4 = (lin & 15) << 2;
        float4 v = *(const float4*)(Qb + (size_t)row * DD + c4);
        split_sts4(sm + F_QH, sm + F_QL, row * 128 + c4 * 2, v);
    }
    // K half-tile 0 (rows 0..63)
#pragma unroll
    for (int i = 0; i < 2; i++) {
        int lin = tid + i * 512;
        int row = lin >> 4, c4 = (lin & 15) << 2;
        float4 v = *(const float4*)(Kb + (size_t)row * DD + c4);
        split_sts4(sm + F_KH, sm + F_KL, row * 128 + c4 * 2, v);
    }
    FENCE_ASYNC();
    __syncthreads();

    auto issue_qk = [&](uint32_t dst, uint32_t bar) {
        uint64_t ah = make_desc(sbase + F_QH), al = make_desc(sbase + F_QL);
        uint64_t bhd = make_desc(sbase + F_KH), bld = make_desc(sbase + F_KL);
#pragma unroll
        for (int k = 0; k < 4; k++) mma_f16_ss(dst, ah + k * 2, bhd + k * 2, IDESC_64, k > 0);
#pragma unroll
        for (int k = 0; k < 4; k++) mma_f16_ss(dst, ah + k * 2, bld + k * 2, IDESC_64, 1);
#pragma unroll
        for (int k = 0; k < 4; k++) mma_f16_ss(dst, al + k * 2, bhd + k * 2, IDESC_64, 1);
        TC_COMMIT(bar);
    };
    auto issue_pv = [&](int first, uint32_t bar) {
        uint64_t ah = make_desc(sbase + F_PH), al = make_desc(sbase + F_PL);
        uint64_t bhd = make_desc(sbase + F_VH), bld = make_desc(sbase + F_VL);
#pragma unroll
        for (int k = 0; k < 4; k++) mma_f16_ss(T_O, ah + k * 2, bhd + k * 2, IDESC_64, !(first && k == 0));
#pragma unroll
        for (int k = 0; k < 4; k++) mma_f16_ss(T_O, ah + k * 2, bld + k * 2, IDESC_64, 1);
#pragma unroll
        for (int k = 0; k < 4; k++) mma_f16_ss(T_O, al + k * 2, bhd + k * 2, IDESC_64, 1);
        TC_COMMIT(bar);
    };

    if (wid == 0 && elect_one()) issue_qk(T_S, sbase + F_QKB);

    for (int it = 0; it < 32; it++) {
        const int k0 = it * 64;
        MBAR_WAIT0(sbase + F_QKB + it * 8);
        TC_FENCE_AFTER();
        if (it >= 1) MBAR_WAIT0(sbase + F_PVB + (it - 1) * 8);

        // K half-tile it+1 (QK(it) done reading the single K buffer)
        if (it < 31) {
            const float* Kt = Kb + (size_t)(k0 + 64) * DD;
#pragma unroll
            for (int i = 0; i < 2; i++) {
                int lin = tid + i * 512;
                int row = lin >> 4, c4 = (lin & 15) << 2;
                float4 v = *(const float4*)(Kt + (size_t)row * DD + c4);
                split_sts4(sm + F_KH, sm + F_KL, row * 128 + c4 * 2, v);
            }
        }
        // V half-tile it: rows k0..k0+63, transposed [n][k] (PV(it-1) done)
#pragma unroll
        for (int i = 0; i < 2; i++) {
            int lin = tid + i * 512;
            int kr = lin >> 4, n4 = (lin & 15) << 2;
            float4 v = *(const float4*)(Vb + (size_t)(k0 + kr) * DD + n4);
            float vv[4] = {v.x, v.y, v.z, v.w};
#pragma unroll
            for (int j = 0; j < 4; j++) {
                int sw = sw128((n4 + j) * 128 + kr * 2);
                __nv_bfloat16 hh = __float2bfloat16(vv[j]);
                float lo = vv[j] - __bfloat162float(hh);
                *(__nv_bfloat16*)(sm + F_VH + sw) = hh;
                *(__nv_bfloat16*)(sm + F_VL + sw) = __float2bfloat16(lo);
            }
        }
        FENCE_ASYNC();
        __syncthreads();
        if (it < 31 && wid == 0 && elect_one())
            issue_qk(T_S + ((it + 1) & 1) * 64, sbase + F_QKB + (it + 1) * 8);

        // epilogue: S(it) -> exp * inv -> attn (single write) + split into P
        // 4 warp-groups x 16 cols each
        {
            const float iv = invS[myrow];
            uint32_t r[16];
            TC_LD_X16(r, T_S + (it & 1) * 64 + wg * 16);
            TC_WAIT_LD();
            float e[16];
#pragma unroll
            for (int j = 0; j < 16; j++) e[j] = __expf(__uint_as_float(r[j])) * iv;
            float* erow = Eb + (size_t)myrow * LL + k0 + wg * 16;
#pragma unroll
            for (int q = 0; q < 4; q++)
                *(float4*)(erow + q * 4) =
                    make_float4(e[q * 4], e[q * 4 + 1], e[q * 4 + 2], e[q * 4 + 3]);
#pragma unroll
            for (int q = 0; q < 4; q++)
                split_sts4(sm + F_PH, sm + F_PL, myrow * 128 + (wg * 16 + q * 4) * 2,
                           make_float4(e[q * 4], e[q * 4 + 1], e[q * 4 + 2], e[q * 4 + 3]));
        }
        TC_FENCE_BEFORE();
        FENCE_ASYNC();
        __syncthreads();
        if (wid == 0 && elect_one()) issue_pv(it == 0, sbase + F_PVB + it * 8);
    }

    MBAR_WAIT0(sbase + F_PVB + 31 * 8);
    TC_FENCE_AFTER();
    {
        uint32_t r[16];
        TC_LD_X16(r, T_O + wg * 16);
        TC_WAIT_LD();
        TC_FENCE_BEFORE();
        float* orow = Ob + (size_t)myrow * DD + wg * 16;
#pragma unroll
        for (int q = 0; q < 4; q++)
            *(float4*)(orow + q * 4) = make_float4(__uint_as_float(r[q * 4]),
                                                   __uint_as_float(r[q * 4 + 1]),
                                                   __uint_as_float(r[q * 4 + 2]),
                                                   __uint_as_float(r[q * 4 + 3]));
    }
    __syncthreads();
    if (tid == 0) {
#pragma unroll
        for (int i = 0; i < 32; i++) { MBAR_INVAL(sbase + F_QKB + i * 8); MBAR_INVAL(sbase + F_PVB + i * 8); }
    }
    __syncthreads();
    if (wid == 0) { TC_DEALLOC(tbase, 256); }

#else  // scalar fallback
    float* Ts = (float*)sm;
    float q[DD], acc[DD];
    float iv = 0.f;
    if (tid < 128) {
#pragma unroll
        for (int d = 0; d < DD; d++) { q[d] = Qb[(size_t)tid * DD + d]; acc[d] = 0.f; }
        iv = g_inv[bh * LL + tileM + tid];
    }
    float* erow = Eb + (size_t)tid * LL;
    for (int nt = 0; nt < 16; nt++) {
        for (int lin = tid; lin < 128 * 16; lin += blockDim.x) {
            int row = lin >> 4, c4 = (lin & 15) << 2;
            *(float4*)(Ts + row * DD + c4) =
                *(const float4*)(Kb + (size_t)(nt * 128 + row) * DD + c4);
        }
        __syncthreads();
        float p[128];
        if (tid < 128) {
            for (int j = 0; j < 128; j++) {
                float s = 0.f;
#pragma unroll
                for (int d = 0; d < DD; d++) s = fmaf(q[d], Ts[j * DD + d], s);
                p[j] = __expf(s) * iv;
                erow[nt * 128 + j] = p[j];
            }
        }
        __syncthreads();
        for (int lin = tid; lin < 128 * 16; lin += blockDim.x) {
            int row = lin >> 4, c4 = (lin & 15) << 2;
            *(float4*)(Ts + row * DD + c4) =
                *(const float4*)(Vb + (size_t)(nt * 128 + row) * DD + c4);
        }
        __syncthreads();
        if (tid < 128) {
            for (int j = 0; j < 128; j++)
#pragma unroll
                for (int d = 0; d < DD; d++) acc[d] = fmaf(p[j], Ts[j * DD + d], acc[d]);
        }
        __syncthreads();
    }
    if (tid < 128) {
#pragma unroll
        for (int d = 0; d < DD; d += 4)
            *(float4*)(Ob + (size_t)tid * DD + d) =
                make_float4(acc[d], acc[d + 1], acc[d + 2], acc[d + 3]);
    }
#endif
}

// ---------------------------------------------------------------------------
// ctx-only fallback: fused per-row attention (rarely used branch).
// ---------------------------------------------------------------------------
__global__ __launch_bounds__(256) void fused_ctx_kernel(const float* __restrict__ Q,
                                                        const float* __restrict__ K,
                                                        const float* __restrict__ V,
                                                        float* __restrict__ O) {
    __shared__ float q[DD];
    __shared__ float s[LL];
    __shared__ float wred[8];
    __shared__ float bcast;

    const int bh = blockIdx.y;
    const int qi = blockIdx.x;
    const float* Qb = Q + ((size_t)bh * LL + qi) * DD;
    const float* Kb = K + (size_t)bh * LL * DD;
    const float* Vb = V + (size_t)bh * LL * DD;
    float* Ob = O + ((size_t)bh * LL + qi) * DD;

    const int tid = threadIdx.x;
    const int warp = tid >> 5, lane = tid & 31;
    if (tid < DD) q[tid] = Qb[tid];
    __syncthreads();

    float m = -CUDART_INF_F;
    for (int j = tid; j < LL; j += 256) {
        float d = 0.f;
#pragma unroll
        for (int d0 = 0; d0 < DD; d0++) d = fmaf(q[d0], Kb[(size_t)j * DD + d0], d);
        s[j] = d;
        m = fmaxf(m, d);
    }
#pragma unroll
    for (int o = 16; o > 0; o >>= 1) m = fmaxf(m, __shfl_xor_sync(0xffffffffu, m, o));
    if (lane == 0) wred[warp] = m;
    __syncthreads();
    if (warp == 0) {
        float x = (lane < 8) ? wred[lane] : -CUDART_INF_F;
#pragma unroll
        for (int o = 4; o > 0; o >>= 1) x = fmaxf(x, __shfl_xor_sync(0xffffffffu, x, o));
        if (lane == 0) bcast = x;
    }
    __syncthreads();
    m = bcast;

    float ssum = 0.f;
    for (int j = tid; j < LL; j += 256) {
        float e = __expf(s[j] - m);
        s[j] = e;
        ssum += e;
    }
#pragma unroll
    for (int o = 16; o > 0; o >>= 1) ssum += __shfl_xor_sync(0xffffffffu, ssum, o);
    __syncthreads();
    if (lane == 0) wred[warp] = ssum;
    __syncthreads();
    if (warp == 0) {
        float x = (lane < 8) ? wred[lane] : 0.f;
#pragma unroll
        for (int o = 4; o > 0; o >>= 1) x += __shfl_xor_sync(0xffffffffu, x, o);
        if (lane == 0) bcast = 1.f / x;
    }
    __syncthreads();
    const float inv = bcast;

    if (tid < DD) {
        float a = 0.f;
        for (int j = 0; j < LL; j++) a = fmaf(s[j], Vb[(size_t)j * DD + tid], a);
        Ob[tid] = a * inv;
    }
}

// ---------------------------------------------------------------------------
extern "C" void kernel_launch(void* const* d_in, const int* in_sizes, int n_in,
                              void* d_out, int out_size) {
    const float* Q = (const float*)d_in[0];
    const float* K = (const float*)d_in[1];
    const float* V = (const float*)d_in[2];
    float* out = (float*)d_out;

    cudaFuncSetAttribute(qk_rowsum_tc, cudaFuncAttributeMaxDynamicSharedMemorySize, QK_SMEM);
    cudaFuncSetAttribute(fused_pv_tc, cudaFuncAttributeMaxDynamicSharedMemorySize, F_SMEM);

    if ((size_t)out_size >= CTX_ELEMS + ATT_ELEMS) {
        float* ctx = out;
        float* att = out + CTX_ELEMS;
        qk_rowsum_tc<<<dim3(16, BHN), 512, QK_SMEM>>>(Q, K);
        fused_pv_tc<<<dim3(16, BHN), 512, F_SMEM>>>(Q, K, V, att, ctx);
    } else if ((size_t)out_size == ATT_ELEMS) {
        float* scratch = nullptr;
        cudaGetSymbolAddress((void**)&scratch, g_ctx_scratch);
        qk_rowsum_tc<<<dim3(16, BHN), 512, QK_SMEM>>>(Q, K);
        fused_pv_tc<<<dim3(16, BHN), 512, F_SMEM>>>(Q, K, V, out, scratch);
    } else {
        fused_ctx_kernel<<<dim3(LL, BHN), 256>>>(Q, K, V, out);
    }
}

// round 13
// speedup vs baseline: 1.5297x; 1.0002x over previous
#include <cuda_runtime.h>
#include <cuda_bf16.h>
#include <math_constants.h>
#include <cstdint>

// Problem shape: B=4, H=16, L=2048, D=64 (fp32)
#define BHN 64
#define LL  2048
#define DD  64

static const size_t CTX_ELEMS = (size_t)BHN * LL * DD;          // 8,388,608
static const size_t ATT_ELEMS = (size_t)BHN * LL * (size_t)LL;  // 268,435,456

// scratch (static __device__, allowed)
__device__ float g_inv[BHN * LL];                       // per-row 1/rowsum
__device__ float g_ctx_scratch[(size_t)BHN * LL * DD];  // ctx sink for attn-only

#if defined(__CUDA_ARCH_FEAT_SM103_ALL) || defined(__CUDA_ARCH_FEAT_SM100_ALL) || defined(__CUDA_ARCH_FEAT_SM101_ALL)
#define HAS_TC 1
#else
#define HAS_TC 0
#endif

// ===================== SMEM layouts =====================
// K1 (rowsum): [tmem][16 mbars][rowsum 512f][Q hi/lo 32K][Kbuf0 32K][Kbuf1 32K]
#define QK_TMEM 0
#define QK_MBAR 16
#define QK_RS   1024                      /* 512 floats = 2048 B */
#define QK_QH   4096
#define QK_QL   (QK_QH + 16384)
#define QK_KB0  36864
#define QK_KB1  69632
#define QK_SMEM 102400
// K2 (fused recompute+PV):
// [tmem][32 QK bars][32 PV bars][inv 512B] | Qh Ql | Kh Kl | Ph Pl | Vh Vl
#define F_TMEM 0
#define F_QKB  16
#define F_PVB  (F_QKB + 32 * 8)
#define F_INV  (F_PVB + 32 * 8)
#define F_QH   2048
#define F_QL   (F_QH + 16384)
#define F_KH   34816
#define F_KL   (F_KH + 8192)
#define F_PH   51200
#define F_PL   (F_PH + 16384)
#define F_VH   83968
#define F_VL   (F_VH + 8192)
#define F_SMEM 100352

#if HAS_TC
// ===================== PTX helpers =====================
__device__ __forceinline__ uint32_t smem_u32(const void* p) {
    uint32_t a;
    asm("{ .reg .u64 t; cvta.to.shared.u64 t, %1; cvt.u32.u64 %0, t; }" : "=r"(a) : "l"(p));
    return a;
}
__device__ __forceinline__ uint32_t elect_one() {
    uint32_t p;
    asm volatile("{\n\t.reg .pred p;\n\telect.sync _|p, 0xFFFFFFFF;\n\tselp.b32 %0, 1, 0, p;\n\t}" : "=r"(p));
    return p;
}
#define TC_ALLOC(sa, n)  asm volatile("tcgen05.alloc.cta_group::1.sync.aligned.shared::cta.b32 [%0], %1;" :: "r"(sa), "r"(n) : "memory")
#define TC_DEALLOC(t, n) asm volatile("tcgen05.dealloc.cta_group::1.sync.aligned.b32 %0, %1;" :: "r"(t), "r"(n))
#define TC_COMMIT(mb)    asm volatile("tcgen05.commit.cta_group::1.mbarrier::arrive::one.shared::cluster.b64 [%0];" :: "r"(mb) : "memory")
#define TC_WAIT_LD()     asm volatile("tcgen05.wait::ld.sync.aligned;" ::: "memory")
#define TC_FENCE_AFTER() asm volatile("tcgen05.fence::after_thread_sync;" ::: "memory")
#define TC_FENCE_BEFORE() asm volatile("tcgen05.fence::before_thread_sync;" ::: "memory")
#define FENCE_ASYNC()    asm volatile("fence.proxy.async.shared::cta;" ::: "memory")
#define MBAR_INIT(mb, c) asm volatile("mbarrier.init.shared.b64 [%0], %1;" :: "r"(mb), "r"(c) : "memory")
#define MBAR_INVAL(mb)   asm volatile("mbarrier.inval.shared.b64 [%0];" :: "r"(mb) : "memory")

#define MBAR_WAIT0(mb) do {                                                  \
    uint32_t _mb = (mb); uint32_t _done;                                     \
    asm volatile("{\n\t.reg .pred p;\n\t"                                    \
        "mbarrier.try_wait.parity.acquire.cta.shared::cta.b64 p, [%1], 0;\n\t" \
        "selp.b32 %0, 1, 0, p;\n\t}"                                         \
        : "=r"(_done) : "r"(_mb) : "memory");                                \
    if (!_done) {                                                            \
        asm volatile("{\n\t.reg .pred P1;\n\t"                               \
            "WL_%=:\n\t"                                                     \
            "mbarrier.try_wait.parity.acquire.cta.shared::cta.b64 P1, [%0], 0, 0x989680;\n\t" \
            "@P1 bra.uni WD_%=;\n\t"                                         \
            "bra.uni WL_%=;\n\t"                                             \
            "WD_%=:\n\t}"                                                    \
            :: "r"(_mb) : "memory");                                         \
    }                                                                        \
} while (0)

#define TC_LD_X16(r, ta) \
    asm volatile( \
        "tcgen05.ld.sync.aligned.32x32b.x16.b32 " \
        "{%0, %1, %2, %3, %4, %5, %6, %7, " \
        " %8, %9, %10, %11, %12, %13, %14, %15}, [%16];" \
        : "=r"((r)[0]),  "=r"((r)[1]),  "=r"((r)[2]),  "=r"((r)[3]), \
          "=r"((r)[4]),  "=r"((r)[5]),  "=r"((r)[6]),  "=r"((r)[7]), \
          "=r"((r)[8]),  "=r"((r)[9]),  "=r"((r)[10]), "=r"((r)[11]), \
          "=r"((r)[12]), "=r"((r)[13]), "=r"((r)[14]), "=r"((r)[15]) \
        : "r"(ta))

__device__ __forceinline__ void mma_f16_ss(uint32_t d, uint64_t ad, uint64_t bd,
                                           uint32_t idesc, uint32_t acc) {
    asm volatile(
        "{\n\t.reg .pred p;\n\tsetp.ne.u32 p, %4, 0;\n\t"
        "tcgen05.mma.cta_group::1.kind::f16 [%0], %1, %2, %3, {%5, %5, %5, %5}, p;\n\t}"
        :: "r"(d), "l"(ad), "l"(bd), "r"(idesc), "r"(acc), "r"(0u)
        : "memory");
}

__device__ __forceinline__ uint64_t make_desc(uint32_t addr) {
    return 0x4000404000010000ULL | (uint64_t)((addr >> 4) & 0x3FFF);
}
__device__ __forceinline__ int sw128(int off) { return off ^ ((off >> 3) & 0x70); }

// M=128, N=64 bf16->f32 (proven geometry)
#define IDESC_64 0x8100490u

__device__ __forceinline__ void split_sts4(char* hi_base, char* lo_base, int byte_off, float4 v) {
    int sw = sw128(byte_off);
    __nv_bfloat16 h0 = __float2bfloat16(v.x), h1 = __float2bfloat16(v.y),
                  h2 = __float2bfloat16(v.z), h3 = __float2bfloat16(v.w);
    float l0 = v.x - __bfloat162float(h0), l1 = v.y - __bfloat162float(h1),
          l2 = v.z - __bfloat162float(h2), l3 = v.w - __bfloat162float(h3);
    __nv_bfloat16 g0 = __float2bfloat16(l0), g1 = __float2bfloat16(l1),
                  g2 = __float2bfloat16(l2), g3 = __float2bfloat16(l3);
    uint2 hv, lv;
    hv.x = (uint32_t)__bfloat16_as_ushort(h0) | ((uint32_t)__bfloat16_as_ushort(h1) << 16);
    hv.y = (uint32_t)__bfloat16_as_ushort(h2) | ((uint32_t)__bfloat16_as_ushort(h3) << 16);
    lv.x = (uint32_t)__bfloat16_as_ushort(g0) | ((uint32_t)__bfloat16_as_ushort(g1) << 16);
    lv.y = (uint32_t)__bfloat16_as_ushort(g2) | ((uint32_t)__bfloat16_as_ushort(g3) << 16);
    *(uint2*)(hi_base + sw) = hv;
    *(uint2*)(lo_base + sw) = lv;
}
#endif  // HAS_TC

// ===================== K1: rowsums of exp(Q K^T) -> g_inv (no E store) ====
// grid (16, 64), 512 threads, 2 CTAs/SM (64-reg budget).
__global__ __launch_bounds__(512, 2) __cluster_dims__(1, 1, 1)
void qk_rowsum_tc(const float* __restrict__ Q, const float* __restrict__ K) {
    extern __shared__ char sm[];
    const int tid = threadIdx.x, wid = tid >> 5, lid = tid & 31;
    const int bh = blockIdx.y, tileM = blockIdx.x * 128;
    const float* Qb = Q + ((size_t)bh * LL + tileM) * DD;
    const float* Kb = K + (size_t)bh * LL * DD;

#if HAS_TC
    const uint32_t sbase = smem_u32(sm);
    const int wg = wid >> 2;                 // 0..3 -> cols wg*32..wg*32+31
    const int myrow = (wid & 3) * 32 + lid;

    if (wid == 0) { TC_ALLOC(sbase + QK_TMEM, 256); }
    if (tid == 0) {
#pragma unroll
        for (int i = 0; i < 16; i++) MBAR_INIT(sbase + QK_MBAR + i * 8, 1);
    }
    __syncthreads();
    uint32_t tbase;
    asm volatile("ld.shared.b32 %0, [%1];" : "=r"(tbase) : "r"(sbase + QK_TMEM));

#pragma unroll
    for (int i = 0; i < 4; i++) {
        int lin = tid + i * 512;
        int row = lin >> 4, c4 = (lin & 15) << 2;
        float4 v = *(const float4*)(Qb + (size_t)row * DD + c4);
        split_sts4(sm + QK_QH, sm + QK_QL, row * 128 + c4 * 2, v);
    }
#pragma unroll
    for (int i = 0; i < 4; i++) {
        int lin = tid + i * 512;
        int row = lin >> 4, c4 = (lin & 15) << 2;
        float4 v = *(const float4*)(Kb + (size_t)row * DD + c4);
        split_sts4(sm + QK_KB0, sm + QK_KB0 + 16384, row * 128 + c4 * 2, v);
    }
    FENCE_ASYNC();
    __syncthreads();

    auto issue_qk = [&](uint32_t kbase, uint32_t dst, uint32_t bar) {
        uint64_t ah = make_desc(sbase + QK_QH), al = make_desc(sbase + QK_QL);
#pragma unroll
        for (int n = 0; n < 2; n++) {
            uint64_t bhd = make_desc(kbase + n * 8192);
            uint64_t bld = make_desc(kbase + 16384 + n * 8192);
            uint32_t d = dst + n * 64;
#pragma unroll
            for (int k = 0; k < 4; k++) mma_f16_ss(d, ah + k * 2, bhd + k * 2, IDESC_64, k > 0);
#pragma unroll
            for (int k = 0; k < 4; k++) mma_f16_ss(d, ah + k * 2, bld + k * 2, IDESC_64, 1);
#pragma unroll
            for (int k = 0; k < 4; k++) mma_f16_ss(d, al + k * 2, bhd + k * 2, IDESC_64, 1);
        }
        TC_COMMIT(bar);
    };

    if (wid == 0 && elect_one()) issue_qk(sbase + QK_KB0, tbase, sbase + QK_MBAR);

    float rs = 0.f;
    for (int nt = 0; nt < 16; nt++) {
        if (nt < 15) {
            const float* Kt = Kb + (size_t)(nt + 1) * 128 * DD;
            uint32_t kb = ((nt + 1) & 1) ? QK_KB1 : QK_KB0;
#pragma unroll
            for (int i = 0; i < 4; i++) {
                int lin = tid + i * 512;
                int row = lin >> 4, c4 = (lin & 15) << 2;
                float4 v = *(const float4*)(Kt + (size_t)row * DD + c4);
                split_sts4(sm + kb, sm + kb + 16384, row * 128 + c4 * 2, v);
            }
            FENCE_ASYNC();
        }
        __syncthreads();
        if (nt < 15 && wid == 0 && elect_one()) {
            uint32_t kb = ((nt + 1) & 1) ? QK_KB1 : QK_KB0;
            issue_qk(sbase + kb, tbase + ((nt + 1) & 1) * 128, sbase + QK_MBAR + (nt + 1) * 8);
        }
        MBAR_WAIT0(sbase + QK_MBAR + nt * 8);
        TC_FENCE_AFTER();

        // 4 warp-groups x 32 cols each (two x16 batches to cap live regs)
#pragma unroll
        for (int h = 0; h < 2; h++) {
            uint32_t r[16];
            TC_LD_X16(r, tbase + (nt & 1) * 128 + wg * 32 + h * 16);
            TC_WAIT_LD();
#pragma unroll
            for (int j = 0; j < 16; j++) rs += __expf(__uint_as_float(r[j]));
        }
        TC_FENCE_BEFORE();
    }

    float* rsbuf = (float*)(sm + QK_RS);
    rsbuf[wg * 128 + myrow] = rs;
    __syncthreads();
    if (wg == 0)
        g_inv[bh * LL + tileM + myrow] =
            1.0f / (rsbuf[myrow] + rsbuf[128 + myrow] + rsbuf[256 + myrow] + rsbuf[384 + myrow]);

    __syncthreads();
    if (tid == 0) {
#pragma unroll
        for (int i = 0; i < 16; i++) MBAR_INVAL(sbase + QK_MBAR + i * 8);
    }
    __syncthreads();
    if (wid == 0) { TC_DEALLOC(tbase, 256); }

#else  // scalar fallback
    float* Ts = (float*)sm;
    float q[DD];
    if (tid < 128) {
#pragma unroll
        for (int d = 0; d < DD; d++) q[d] = Qb[(size_t)tid * DD + d];
    }
    float rs = 0.f;
    for (int nt = 0; nt < 16; nt++) {
        for (int lin = tid; lin < 128 * 16; lin += blockDim.x) {
            int row = lin >> 4, c4 = (lin & 15) << 2;
            *(float4*)(Ts + row * DD + c4) =
                *(const float4*)(Kb + (size_t)(nt * 128 + row) * DD + c4);
        }
        __syncthreads();
        if (tid < 128) {
            for (int j = 0; j < 128; j++) {
                float s = 0.f;
#pragma unroll
                for (int d = 0; d < DD; d++) s = fmaf(q[d], Ts[j * DD + d], s);
                rs += __expf(s);
            }
        }
        __syncthreads();
    }
    if (tid < 128) g_inv[bh * LL + tileM + tid] = 1.0f / rs;
#endif
}

// ========== K2: recompute QK, write normalized attn once, PV accumulate ====
// grid (16, 64), 512 threads, 2 CTAs/SM (64-reg budget).
__global__ __launch_bounds__(512, 2) __cluster_dims__(1, 1, 1)
void fused_pv_tc(const float* __restrict__ Q, const float* __restrict__ K,
                 const float* __restrict__ V, float* __restrict__ att,
                 float* __restrict__ ctx) {
    extern __shared__ char sm[];
    const int tid = threadIdx.x, wid = tid >> 5, lid = tid & 31;
    const int bh = blockIdx.y, tileM = blockIdx.x * 128;
    const float* Qb = Q + ((size_t)bh * LL + tileM) * DD;
    const float* Kb = K + (size_t)bh * LL * DD;
    const float* Vb = V + (size_t)bh * LL * DD;
    float* Eb = att + ((size_t)bh * LL + tileM) * LL;
    float* Ob = ctx + ((size_t)bh * LL + tileM) * DD;

#if HAS_TC
    const uint32_t sbase = smem_u32(sm);
    const int wg = wid >> 2;                 // 0..3 -> cols wg*16..wg*16+15
    const int myrow = (wid & 3) * 32 + lid;

    if (wid == 0) { TC_ALLOC(sbase + F_TMEM, 256); }
    if (tid == 0) {
#pragma unroll
        for (int i = 0; i < 32; i++) { MBAR_INIT(sbase + F_QKB + i * 8, 1); MBAR_INIT(sbase + F_PVB + i * 8, 1); }
    }
    float* invS = (float*)(sm + F_INV);
    if (tid < 128) invS[tid] = g_inv[bh * LL + tileM + tid];
    __syncthreads();
    uint32_t tbase;
    asm volatile("ld.shared.b32 %0, [%1];" : "=r"(tbase) : "r"(sbase + F_TMEM));
    const uint32_t T_S = tbase;          // Sbuf0 @ +0, Sbuf1 @ +64
    const uint32_t T_O = tbase + 128;    // O accumulator, 64 cols

    // resident Q tile
#pragma unroll
    for (int i = 0; i < 4; i++) {
        int lin = tid + i * 512;
        int row = lin >> 4, c4 = (lin & 15) << 2;
        float4 v = *(const float4*)(Qb + (size_t)row * DD + c4);
        split_sts4(sm + F_QH, sm + F_QL, row * 128 + c4 * 2, v);
    }
    // K half-tile 0 (rows 0..63)
#pragma unroll
    for (int i = 0; i < 2; i++) {
        int lin = tid + i * 512;
        int row = lin >> 4, c4 = (lin & 15) << 2;
        float4 v = *(const float4*)(Kb + (size_t)row * DD + c4);
        split_sts4(sm + F_KH, sm + F_KL, row * 128 + c4 * 2, v);
    }
    FENCE_ASYNC();
    __syncthreads();

    auto issue_qk = [&](uint32_t dst, uint32_t bar) {
        uint64_t ah = make_desc(sbase + F_QH), al = make_desc(sbase + F_QL);
        uint64_t bhd = make_desc(sbase + F_KH), bld = make_desc(sbase + F_KL);
#pragma unroll
        for (int k = 0; k < 4; k++) mma_f16_ss(dst, ah + k * 2, bhd + k * 2, IDESC_64, k > 0);
#pragma unroll
        for (int k = 0; k < 4; k++) mma_f16_ss(dst, ah + k * 2, bld + k * 2, IDESC_64, 1);
#pragma unroll
        for (int k = 0; k < 4; k++) mma_f16_ss(dst, al + k * 2, bhd + k * 2, IDESC_64, 1);
        TC_COMMIT(bar);
    };
    auto issue_pv = [&](int first, uint32_t bar) {
        uint64_t ah = make_desc(sbase + F_PH), al = make_desc(sbase + F_PL);
        uint64_t bhd = make_desc(sbase + F_VH), bld = make_desc(sbase + F_VL);
#pragma unroll
        for (int k = 0; k < 4; k++) mma_f16_ss(T_O, ah + k * 2, bhd + k * 2, IDESC_64, !(first && k == 0));
#pragma unroll
        for (int k = 0; k < 4; k++) mma_f16_ss(T_O, ah + k * 2, bld + k * 2, IDESC_64, 1);
#pragma unroll
        for (int k = 0; k < 4; k++) mma_f16_ss(T_O, al + k * 2, bhd + k * 2, IDESC_64, 1);
        TC_COMMIT(bar);
    };

    if (wid == 0 && elect_one()) issue_qk(T_S, sbase + F_QKB);

    for (int it = 0; it < 32; it++) {
        const int k0 = it * 64;
        MBAR_WAIT0(sbase + F_QKB + it * 8);
        TC_FENCE_AFTER();
        if (it >= 1) MBAR_WAIT0(sbase + F_PVB + (it - 1) * 8);

        // K half-tile it+1 (QK(it) done reading the single K buffer)
        if (it < 31) {
            const float* Kt = Kb + (size_t)(k0 + 64) * DD;
#pragma unroll
            for (int i = 0; i < 2; i++) {
                int lin = tid + i * 512;
                int row = lin >> 4, c4 = (lin & 15) << 2;
                float4 v = *(const float4*)(Kt + (size_t)row * DD + c4);
                split_sts4(sm + F_KH, sm + F_KL, row * 128 + c4 * 2, v);
            }
        }
        // V half-tile it: rows k0..k0+63, transposed [n][k] (PV(it-1) done)
#pragma unroll
        for (int i = 0; i < 2; i++) {
            int lin = tid + i * 512;
            int kr = lin >> 4, n4 = (lin & 15) << 2;
            float4 v = *(const float4*)(Vb + (size_t)(k0 + kr) * DD + n4);
            float vv[4] = {v.x, v.y, v.z, v.w};
#pragma unroll
            for (int j = 0; j < 4; j++) {
                int sw = sw128((n4 + j) * 128 + kr * 2);
                __nv_bfloat16 hh = __float2bfloat16(vv[j]);
                float lo = vv[j] - __bfloat162float(hh);
                *(__nv_bfloat16*)(sm + F_VH + sw) = hh;
                *(__nv_bfloat16*)(sm + F_VL + sw) = __float2bfloat16(lo);
            }
        }
        FENCE_ASYNC();
        __syncthreads();
        if (it < 31 && wid == 0 && elect_one())
            issue_qk(T_S + ((it + 1) & 1) * 64, sbase + F_QKB + (it + 1) * 8);

        // epilogue: S(it) -> exp * inv -> attn (single write) + split into P
        // 4 warp-groups x 16 cols each
        {
            const float iv = invS[myrow];
            uint32_t r[16];
            TC_LD_X16(r, T_S + (it & 1) * 64 + wg * 16);
            TC_WAIT_LD();
            float e[16];
#pragma unroll
            for (int j = 0; j < 16; j++) e[j] = __expf(__uint_as_float(r[j])) * iv;
            float* erow = Eb + (size_t)myrow * LL + k0 + wg * 16;
#pragma unroll
            for (int q = 0; q < 4; q++)
                *(float4*)(erow + q * 4) =
                    make_float4(e[q * 4], e[q * 4 + 1], e[q * 4 + 2], e[q * 4 + 3]);
#pragma unroll
            for (int q = 0; q < 4; q++)
                split_sts4(sm + F_PH, sm + F_PL, myrow * 128 + (wg * 16 + q * 4) * 2,
                           make_float4(e[q * 4], e[q * 4 + 1], e[q * 4 + 2], e[q * 4 + 3]));
        }
        TC_FENCE_BEFORE();
        FENCE_ASYNC();
        __syncthreads();
        if (wid == 0 && elect_one()) issue_pv(it == 0, sbase + F_PVB + it * 8);
    }

    MBAR_WAIT0(sbase + F_PVB + 31 * 8);
    TC_FENCE_AFTER();
    {
        uint32_t r[16];
        TC_LD_X16(r, T_O + wg * 16);
        TC_WAIT_LD();
        TC_FENCE_BEFORE();
        float* orow = Ob + (size_t)myrow * DD + wg * 16;
#pragma unroll
        for (int q = 0; q < 4; q++)
            *(float4*)(orow + q * 4) = make_float4(__uint_as_float(r[q * 4]),
                                                   __uint_as_float(r[q * 4 + 1]),
                                                   __uint_as_float(r[q * 4 + 2]),
                                                   __uint_as_float(r[q * 4 + 3]));
    }
    __syncthreads();
    if (tid == 0) {
#pragma unroll
        for (int i = 0; i < 32; i++) { MBAR_INVAL(sbase + F_QKB + i * 8); MBAR_INVAL(sbase + F_PVB + i * 8); }
    }
    __syncthreads();
    if (wid == 0) { TC_DEALLOC(tbase, 256); }

#else  // scalar fallback
    float* Ts = (float*)sm;
    float q[DD], acc[DD];
    float iv = 0.f;
    if (tid < 128) {
#pragma unroll
        for (int d = 0; d < DD; d++) { q[d] = Qb[(size_t)tid * DD + d]; acc[d] = 0.f; }
        iv = g_inv[bh * LL + tileM + tid];
    }
    float* erow = Eb + (size_t)tid * LL;
    for (int nt = 0; nt < 16; nt++) {
        for (int lin = tid; lin < 128 * 16; lin += blockDim.x) {
            int row = lin >> 4, c4 = (lin & 15) << 2;
            *(float4*)(Ts + row * DD + c4) =
                *(const float4*)(Kb + (size_t)(nt * 128 + row) * DD + c4);
        }
        __syncthreads();
        float p[128];
        if (tid < 128) {
            for (int j = 0; j < 128; j++) {
                float s = 0.f;
#pragma unroll
                for (int d = 0; d < DD; d++) s = fmaf(q[d], Ts[j * DD + d], s);
                p[j] = __expf(s) * iv;
                erow[nt * 128 + j] = p[j];
            }
        }
        __syncthreads();
        for (int lin = tid; lin < 128 * 16; lin += blockDim.x) {
            int row = lin >> 4, c4 = (lin & 15) << 2;
            *(float4*)(Ts + row * DD + c4) =
                *(const float4*)(Vb + (size_t)(nt * 128 + row) * DD + c4);
        }
        __syncthreads();
        if (tid < 128) {
            for (int j = 0; j < 128; j++)
#pragma unroll
                for (int d = 0; d < DD; d++) acc[d] = fmaf(p[j], Ts[j * DD + d], acc[d]);
        }
        __syncthreads();
    }
    if (tid < 128) {
#pragma unroll
        for (int d = 0; d < DD; d += 4)
            *(float4*)(Ob + (size_t)tid * DD + d) =
                make_float4(acc[d], acc[d + 1], acc[d + 2], acc[d + 3]);
    }
#endif
}

// ---------------------------------------------------------------------------
// ctx-only fallback: fused per-row attention (rarely used branch).
// ---------------------------------------------------------------------------
__global__ __launch_bounds__(256) void fused_ctx_kernel(const float* __restrict__ Q,
                                                        const float* __restrict__ K,
                                                        const float* __restrict__ V,
                                                        float* __restrict__ O) {
    __shared__ float q[DD];
    __shared__ float s[LL];
    __shared__ float wred[8];
    __shared__ float bcast;

    const int bh = blockIdx.y;
    const int qi = blockIdx.x;
    const float* Qb = Q + ((size_t)bh * LL + qi) * DD;
    const float* Kb = K + (size_t)bh * LL * DD;
    const float* Vb = V + (size_t)bh * LL * DD;
    float* Ob = O + ((size_t)bh * LL + qi) * DD;

    const int tid = threadIdx.x;
    const int warp = tid >> 5, lane = tid & 31;
    if (tid < DD) q[tid] = Qb[tid];
    __syncthreads();

    float m = -CUDART_INF_F;
    for (int j = tid; j < LL; j += 256) {
        float d = 0.f;
#pragma unroll
        for (int d0 = 0; d0 < DD; d0++) d = fmaf(q[d0], Kb[(size_t)j * DD + d0], d);
        s[j] = d;
        m = fmaxf(m, d);
    }
#pragma unroll
    for (int o = 16; o > 0; o >>= 1) m = fmaxf(m, __shfl_xor_sync(0xffffffffu, m, o));
    if (lane == 0) wred[warp] = m;
    __syncthreads();
    if (warp == 0) {
        float x = (lane < 8) ? wred[lane] : -CUDART_INF_F;
#pragma unroll
        for (int o = 4; o > 0; o >>= 1) x = fmaxf(x, __shfl_xor_sync(0xffffffffu, x, o));
        if (lane == 0) bcast = x;
    }
    __syncthreads();
    m = bcast;

    float ssum = 0.f;
    for (int j = tid; j < LL; j += 256) {
        float e = __expf(s[j] - m);
        s[j] = e;
        ssum += e;
    }
#pragma unroll
    for (int o = 16; o > 0; o >>= 1) ssum += __shfl_xor_sync(0xffffffffu, ssum, o);
    __syncthreads();
    if (lane == 0) wred[warp] = ssum;
    __syncthreads();
    if (warp == 0) {
        float x = (lane < 8) ? wred[lane] : 0.f;
#pragma unroll
        for (int o = 4; o > 0; o >>= 1) x += __shfl_xor_sync(0xffffffffu, x, o);
        if (lane == 0) bcast = 1.f / x;
    }
    __syncthreads();
    const float inv = bcast;

    if (tid < DD) {
        float a = 0.f;
        for (int j = 0; j < LL; j++) a = fmaf(s[j], Vb[(size_t)j * DD + tid], a);
        Ob[tid] = a * inv;
    }
}

// ---------------------------------------------------------------------------
extern "C" void kernel_launch(void* const* d_in, const int* in_sizes, int n_in,
                              void* d_out, int out_size) {
    const float* Q = (const float*)d_in[0];
    const float* K = (const float*)d_in[1];
    const float* V = (const float*)d_in[2];
    float* out = (float*)d_out;

    cudaFuncSetAttribute(qk_rowsum_tc, cudaFuncAttributeMaxDynamicSharedMemorySize, QK_SMEM);
    cudaFuncSetAttribute(fused_pv_tc, cudaFuncAttributeMaxDynamicSharedMemorySize, F_SMEM);

    if ((size_t)out_size >= CTX_ELEMS + ATT_ELEMS) {
        float* ctx = out;
        float* att = out + CTX_ELEMS;
        qk_rowsum_tc<<<dim3(16, BHN), 512, QK_SMEM>>>(Q, K);
        fused_pv_tc<<<dim3(16, BHN), 512, F_SMEM>>>(Q, K, V, att, ctx);
    } else if ((size_t)out_size == ATT_ELEMS) {
        float* scratch = nullptr;
        cudaGetSymbolAddress((void**)&scratch, g_ctx_scratch);
        qk_rowsum_tc<<<dim3(16, BHN), 512, QK_SMEM>>>(Q, K);
        fused_pv_tc<<<dim3(16, BHN), 512, F_SMEM>>>(Q, K, V, out, scratch);
    } else {
        fused_ctx_kernel<<<dim3(LL, BHN), 256>>>(Q, K, V, out);
    }
}

// round 15
// speedup vs baseline: 1.9016x; 1.2432x over previous
#include <cuda_runtime.h>
#include <cuda_bf16.h>
#include <math_constants.h>
#include <cstdint>

// Problem shape: B=4, H=16, L=2048, D=64 (fp32)
#define BHN 64
#define LL  2048
#define DD  64

static const size_t CTX_ELEMS = (size_t)BHN * LL * DD;          // 8,388,608
static const size_t ATT_ELEMS = (size_t)BHN * LL * (size_t)LL;  // 268,435,456

// scratch (static __device__, allowed)
__device__ float g_inv[BHN * LL];                       // per-row 1/rowsum
__device__ float g_ctx_scratch[(size_t)BHN * LL * DD];  // ctx sink for attn-only

#if defined(__CUDA_ARCH_FEAT_SM103_ALL) || defined(__CUDA_ARCH_FEAT_SM100_ALL) || defined(__CUDA_ARCH_FEAT_SM101_ALL)
#define HAS_TC 1
#else
#define HAS_TC 0
#endif

// ===================== SMEM layouts =====================
// K1 (rowsum): [tmem][16 mbars][rowsum 512f][Q hi/lo 32K][Kbuf0 32K][Kbuf1 32K]
#define QK_TMEM 0
#define QK_MBAR 16
#define QK_RS   1024                      /* 512 floats = 2048 B */
#define QK_QH   4096
#define QK_QL   (QK_QH + 16384)
#define QK_KB0  36864
#define QK_KB1  69632
#define QK_SMEM 102400
// K2 (fused recompute+PV):
// [tmem][32 QK bars][32 PV bars][inv 512B] | Qh Ql | Kh Kl | Ph Pl | Vh Vl
#define F_TMEM 0
#define F_QKB  16
#define F_PVB  (F_QKB + 32 * 8)
#define F_INV  (F_PVB + 32 * 8)
#define F_QH   2048
#define F_QL   (F_QH + 16384)
#define F_KH   34816
#define F_KL   (F_KH + 8192)
#define F_PH   51200
#define F_PL   (F_PH + 16384)
#define F_VH   83968
#define F_VL   (F_VH + 8192)
#define F_SMEM 100352

#if HAS_TC
// ===================== PTX helpers =====================
__device__ __forceinline__ uint32_t smem_u32(const void* p) {
    uint32_t a;
    asm("{ .reg .u64 t; cvta.to.shared.u64 t, %1; cvt.u32.u64 %0, t; }" : "=r"(a) : "l"(p));
    return a;
}
__device__ __forceinline__ uint32_t elect_one() {
    uint32_t p;
    asm volatile("{\n\t.reg .pred p;\n\telect.sync _|p, 0xFFFFFFFF;\n\tselp.b32 %0, 1, 0, p;\n\t}" : "=r"(p));
    return p;
}
#define TC_ALLOC(sa, n)  asm volatile("tcgen05.alloc.cta_group::1.sync.aligned.shared::cta.b32 [%0], %1;" :: "r"(sa), "r"(n) : "memory")
#define TC_DEALLOC(t, n) asm volatile("tcgen05.dealloc.cta_group::1.sync.aligned.b32 %0, %1;" :: "r"(t), "r"(n))
#define TC_RELINQ()      asm volatile("tcgen05.relinquish_alloc_permit.cta_group::1.sync.aligned;")
#define TC_COMMIT(mb)    asm volatile("tcgen05.commit.cta_group::1.mbarrier::arrive::one.shared::cluster.b64 [%0];" :: "r"(mb) : "memory")
#define TC_WAIT_LD()     asm volatile("tcgen05.wait::ld.sync.aligned;" ::: "memory")
#define TC_FENCE_AFTER() asm volatile("tcgen05.fence::after_thread_sync;" ::: "memory")
#define TC_FENCE_BEFORE() asm volatile("tcgen05.fence::before_thread_sync;" ::: "memory")
#define FENCE_ASYNC()    asm volatile("fence.proxy.async.shared::cta;" ::: "memory")
#define MBAR_INIT(mb, c) asm volatile("mbarrier.init.shared.b64 [%0], %1;" :: "r"(mb), "r"(c) : "memory")
#define MBAR_INVAL(mb)   asm volatile("mbarrier.inval.shared.b64 [%0];" :: "r"(mb) : "memory")

#define MBAR_WAIT0(mb) do {                                                  \
    uint32_t _mb = (mb); uint32_t _done;                                     \
    asm volatile("{\n\t.reg .pred p;\n\t"                                    \
        "mbarrier.try_wait.parity.acquire.cta.shared::cta.b64 p, [%1], 0;\n\t" \
        "selp.b32 %0, 1, 0, p;\n\t}"                                         \
        : "=r"(_done) : "r"(_mb) : "memory");                                \
    if (!_done) {                                                            \
        asm volatile("{\n\t.reg .pred P1;\n\t"                               \
            "WL_%=:\n\t"                                                     \
            "mbarrier.try_wait.parity.acquire.cta.shared::cta.b64 P1, [%0], 0, 0x989680;\n\t" \
            "@P1 bra.uni WD_%=;\n\t"                                         \
            "bra.uni WL_%=;\n\t"                                             \
            "WD_%=:\n\t}"                                                    \
            :: "r"(_mb) : "memory");                                         \
    }                                                                        \
} while (0)

#define TC_LD_X16(r, ta) \
    asm volatile( \
        "tcgen05.ld.sync.aligned.32x32b.x16.b32 " \
        "{%0, %1, %2, %3, %4, %5, %6, %7, " \
        " %8, %9, %10, %11, %12, %13, %14, %15}, [%16];" \
        : "=r"((r)[0]),  "=r"((r)[1]),  "=r"((r)[2]),  "=r"((r)[3]), \
          "=r"((r)[4]),  "=r"((r)[5]),  "=r"((r)[6]),  "=r"((r)[7]), \
          "=r"((r)[8]),  "=r"((r)[9]),  "=r"((r)[10]), "=r"((r)[11]), \
          "=r"((r)[12]), "=r"((r)[13]), "=r"((r)[14]), "=r"((r)[15]) \
        : "r"(ta))

__device__ __forceinline__ void mma_f16_ss(uint32_t d, uint64_t ad, uint64_t bd,
                                           uint32_t idesc, uint32_t acc) {
    asm volatile(
        "{\n\t.reg .pred p;\n\tsetp.ne.u32 p, %4, 0;\n\t"
        "tcgen05.mma.cta_group::1.kind::f16 [%0], %1, %2, %3, {%5, %5, %5, %5}, p;\n\t}"
        :: "r"(d), "l"(ad), "l"(bd), "r"(idesc), "r"(acc), "r"(0u)
        : "memory");
}

__device__ __forceinline__ uint64_t make_desc(uint32_t addr) {
    return 0x4000404000010000ULL | (uint64_t)((addr >> 4) & 0x3FFF);
}
__device__ __forceinline__ int sw128(int off) { return off ^ ((off >> 3) & 0x70); }

// M=128, N=64 bf16->f32 (proven geometry)
#define IDESC_64 0x8100490u

__device__ __forceinline__ void split_sts4(char* hi_base, char* lo_base, int byte_off, float4 v) {
    int sw = sw128(byte_off);
    __nv_bfloat16 h0 = __float2bfloat16(v.x), h1 = __float2bfloat16(v.y),
                  h2 = __float2bfloat16(v.z), h3 = __float2bfloat16(v.w);
    float l0 = v.x - __bfloat162float(h0), l1 = v.y - __bfloat162float(h1),
          l2 = v.z - __bfloat162float(h2), l3 = v.w - __bfloat162float(h3);
    __nv_bfloat16 g0 = __float2bfloat16(l0), g1 = __float2bfloat16(l1),
                  g2 = __float2bfloat16(l2), g3 = __float2bfloat16(l3);
    uint2 hv, lv;
    hv.x = (uint32_t)__bfloat16_as_ushort(h0) | ((uint32_t)__bfloat16_as_ushort(h1) << 16);
    hv.y = (uint32_t)__bfloat16_as_ushort(h2) | ((uint32_t)__bfloat16_as_ushort(h3) << 16);
    lv.x = (uint32_t)__bfloat16_as_ushort(g0) | ((uint32_t)__bfloat16_as_ushort(g1) << 16);
    lv.y = (uint32_t)__bfloat16_as_ushort(g2) | ((uint32_t)__bfloat16_as_ushort(g3) << 16);
    *(uint2*)(hi_base + sw) = hv;
    *(uint2*)(lo_base + sw) = lv;
}
#endif  // HAS_TC

// ===================== K1: rowsums of exp(Q K^T) -> g_inv (no E store) ====
// grid (16, 64), 512 threads, 2 CTAs/SM.
__global__ __launch_bounds__(512, 2) __cluster_dims__(1, 1, 1)
void qk_rowsum_tc(const float* __restrict__ Q, const float* __restrict__ K) {
    extern __shared__ char sm[];
    const int tid = threadIdx.x, wid = tid >> 5, lid = tid & 31;
    const int bh = blockIdx.y, tileM = blockIdx.x * 128;
    const float* Qb = Q + ((size_t)bh * LL + tileM) * DD;
    const float* Kb = K + (size_t)bh * LL * DD;

#if HAS_TC
    const uint32_t sbase = smem_u32(sm);
    const int wg = wid >> 2;                 // 0..3 -> cols wg*32..wg*32+31
    const int myrow = (wid & 3) * 32 + lid;

    // warp 0 allocs, then immediately relinquishes the alloc permit so a
    // co-resident CTA's alloc can proceed (sequential in one warp: no race).
    if (wid == 0) { TC_ALLOC(sbase + QK_TMEM, 256); TC_RELINQ(); }
    if (tid == 0) {
#pragma unroll
        for (int i = 0; i < 16; i++) MBAR_INIT(sbase + QK_MBAR + i * 8, 1);
    }
    __syncthreads();
    uint32_t tbase;
    asm volatile("ld.shared.b32 %0, [%1];" : "=r"(tbase) : "r"(sbase + QK_TMEM));

#pragma unroll
    for (int i = 0; i < 4; i++) {
        int lin = tid + i * 512;
        int row = lin >> 4, c4 = (lin & 15) << 2;
        float4 v = *(const float4*)(Qb + (size_t)row * DD + c4);
        split_sts4(sm + QK_QH, sm + QK_QL, row * 128 + c4 * 2, v);
    }
#pragma unroll
    for (int i = 0; i < 4; i++) {
        int lin = tid + i * 512;
        int row = lin >> 4, c4 = (lin & 15) << 2;
        float4 v = *(const float4*)(Kb + (size_t)row * DD + c4);
        split_sts4(sm + QK_KB0, sm + QK_KB0 + 16384, row * 128 + c4 * 2, v);
    }
    FENCE_ASYNC();
    __syncthreads();

    auto issue_qk = [&](uint32_t kbase, uint32_t dst, uint32_t bar) {
        uint64_t ah = make_desc(sbase + QK_QH), al = make_desc(sbase + QK_QL);
#pragma unroll
        for (int n = 0; n < 2; n++) {
            uint64_t bhd = make_desc(kbase + n * 8192);
            uint64_t bld = make_desc(kbase + 16384 + n * 8192);
            uint32_t d = dst + n * 64;
#pragma unroll
            for (int k = 0; k < 4; k++) mma_f16_ss(d, ah + k * 2, bhd + k * 2, IDESC_64, k > 0);
#pragma unroll
            for (int k = 0; k < 4; k++) mma_f16_ss(d, ah + k * 2, bld + k * 2, IDESC_64, 1);
#pragma unroll
            for (int k = 0; k < 4; k++) mma_f16_ss(d, al + k * 2, bhd + k * 2, IDESC_64, 1);
        }
        TC_COMMIT(bar);
    };

    if (wid == 0 && elect_one()) issue_qk(sbase + QK_KB0, tbase, sbase + QK_MBAR);

    float rs = 0.f;
    for (int nt = 0; nt < 16; nt++) {
        if (nt < 15) {
            const float* Kt = Kb + (size_t)(nt + 1) * 128 * DD;
            uint32_t kb = ((nt + 1) & 1) ? QK_KB1 : QK_KB0;
#pragma unroll
            for (int i = 0; i < 4; i++) {
                int lin = tid + i * 512;
                int row = lin >> 4, c4 = (lin & 15) << 2;
                float4 v = *(const float4*)(Kt + (size_t)row * DD + c4);
                split_sts4(sm + kb, sm + kb + 16384, row * 128 + c4 * 2, v);
            }
            FENCE_ASYNC();
        }
        __syncthreads();
        if (nt < 15 && wid == 0 && elect_one()) {
            uint32_t kb = ((nt + 1) & 1) ? QK_KB1 : QK_KB0;
            issue_qk(sbase + kb, tbase + ((nt + 1) & 1) * 128, sbase + QK_MBAR + (nt + 1) * 8);
        }
        MBAR_WAIT0(sbase + QK_MBAR + nt * 8);
        TC_FENCE_AFTER();

        // 4 warp-groups x 32 cols each (two x16 batches to cap live regs)
#pragma unroll
        for (int h = 0; h < 2; h++) {
            uint32_t r[16];
            TC_LD_X16(r, tbase + (nt & 1) * 128 + wg * 32 + h * 16);
            TC_WAIT_LD();
#pragma unroll
            for (int j = 0; j < 16; j++) rs += __expf(__uint_as_float(r[j]));
        }
        TC_FENCE_BEFORE();
    }

    float* rsbuf = (float*)(sm + QK_RS);
    rsbuf[wg * 128 + myrow] = rs;
    __syncthreads();
    if (wg == 0)
        g_inv[bh * LL + tileM + myrow] =
            1.0f / (rsbuf[myrow] + rsbuf[128 + myrow] + rsbuf[256 + myrow] + rsbuf[384 + myrow]);

    __syncthreads();
    if (tid == 0) {
#pragma unroll
        for (int i = 0; i < 16; i++) MBAR_INVAL(sbase + QK_MBAR + i * 8);
    }
    __syncthreads();
    if (wid == 0) { TC_DEALLOC(tbase, 256); }

#else  // scalar fallback
    float* Ts = (float*)sm;
    float q[DD];
    if (tid < 128) {
#pragma unroll
        for (int d = 0; d < DD; d++) q[d] = Qb[(size_t)tid * DD + d];
    }
    float rs = 0.f;
    for (int nt = 0; nt < 16; nt++) {
        for (int lin = tid; lin < 128 * 16; lin += blockDim.x) {
            int row = lin >> 4, c4 = (lin & 15) << 2;
            *(float4*)(Ts + row * DD + c4) =
                *(const float4*)(Kb + (size_t)(nt * 128 + row) * DD + c4);
        }
        __syncthreads();
        if (tid < 128) {
            for (int j = 0; j < 128; j++) {
                float s = 0.f;
#pragma unroll
                for (int d = 0; d < DD; d++) s = fmaf(q[d], Ts[j * DD + d], s);
                rs += __expf(s);
            }
        }
        __syncthreads();
    }
    if (tid < 128) g_inv[bh * LL + tileM + tid] = 1.0f / rs;
#endif
}

// ========== K2: recompute QK, write normalized attn once, PV accumulate ====
// grid (16, 64), 512 threads, 2 CTAs/SM.
__global__ __launch_bounds__(512, 2) __cluster_dims__(1, 1, 1)
void fused_pv_tc(const float* __restrict__ Q, const float* __restrict__ K,
                 const float* __restrict__ V, float* __restrict__ att,
                 float* __restrict__ ctx) {
    extern __shared__ char sm[];
    const int tid = threadIdx.x, wid = tid >> 5, lid = tid & 31;
    const int bh = blockIdx.y, tileM = blockIdx.x * 128;
    const float* Qb = Q + ((size_t)bh * LL + tileM) * DD;
    const float* Kb = K + (size_t)bh * LL * DD;
    const float* Vb = V + (size_t)bh * LL * DD;
    float* Eb = att + ((size_t)bh * LL + tileM) * LL;
    float* Ob = ctx + ((size_t)bh * LL + tileM) * DD;

#if HAS_TC
    const uint32_t sbase = smem_u32(sm);
    const int wg = wid >> 2;                 // 0..3 -> cols wg*16..wg*16+15
    const int myrow = (wid & 3) * 32 + lid;

    if (wid == 0) { TC_ALLOC(sbase + F_TMEM, 256); TC_RELINQ(); }
    if (tid == 0) {
#pragma unroll
        for (int i = 0; i < 32; i++) { MBAR_INIT(sbase + F_QKB + i * 8, 1); MBAR_INIT(sbase + F_PVB + i * 8, 1); }
    }
    float* invS = (float*)(sm + F_INV);
    if (tid < 128) invS[tid] = g_inv[bh * LL + tileM + tid];
    __syncthreads();
    uint32_t tbase;
    asm volatile("ld.shared.b32 %0, [%1];" : "=r"(tbase) : "r"(sbase + F_TMEM));
    const uint32_t T_S = tbase;          // Sbuf0 @ +0, Sbuf1 @ +64
    const uint32_t T_O = tbase + 128;    // O accumulator, 64 cols

    // resident Q tile
#pragma unroll
    for (int i = 0; i < 4; i++) {
        int lin = tid + i * 512;
        int row = lin >> 4, c4 = (lin & 15) << 2;
        float4 v = *(const float4*)(Qb + (size_t)row * DD + c4);
        split_sts4(sm + F_QH, sm + F_QL, row * 128 + c4 * 2, v);
    }
    // K half-tile 0 (rows 0..63)
#pragma unroll
    for (int i = 0; i < 2; i++) {
        int lin = tid + i * 512;
        int row = lin >> 4, c4 = (lin & 15) << 2;
        float4 v = *(const float4*)(Kb + (size_t)row * DD + c4);
        split_sts4(sm + F_KH, sm + F_KL, row * 128 + c4 * 2, v);
    }
    FENCE_ASYNC();
    __syncthreads();

    auto issue_qk = [&](uint32_t dst, uint32_t bar) {
        uint64_t ah = make_desc(sbase + F_QH), al = make_desc(sbase + F_QL);
        uint64_t bhd = make_desc(sbase + F_KH), bld = make_desc(sbase + F_KL);
#pragma unroll
        for (int k = 0; k < 4; k++) mma_f16_ss(dst, ah + k * 2, bhd + k * 2, IDESC_64, k > 0);
#pragma unroll
        for (int k = 0; k < 4; k++) mma_f16_ss(dst, ah + k * 2, bld + k * 2, IDESC_64, 1);
#pragma unroll
        for (int k = 0; k < 4; k++) mma_f16_ss(dst, al + k * 2, bhd + k * 2, IDESC_64, 1);
        TC_COMMIT(bar);
    };
    auto issue_pv = [&](int first, uint32_t bar) {
        uint64_t ah = make_desc(sbase + F_PH), al = make_desc(sbase + F_PL);
        uint64_t bhd = make_desc(sbase + F_VH), bld = make_desc(sbase + F_VL);
#pragma unroll
        for (int k = 0; k < 4; k++) mma_f16_ss(T_O, ah + k * 2, bhd + k * 2, IDESC_64, !(first && k == 0));
#pragma unroll
        for (int k = 0; k < 4; k++) mma_f16_ss(T_O, ah + k * 2, bld + k * 2, IDESC_64, 1);
#pragma unroll
        for (int k = 0; k < 4; k++) mma_f16_ss(T_O, al + k * 2, bhd + k * 2, IDESC_64, 1);
        TC_COMMIT(bar);
    };

    if (wid == 0 && elect_one()) issue_qk(T_S, sbase + F_QKB);

    for (int it = 0; it < 32; it++) {
        const int k0 = it * 64;
        MBAR_WAIT0(sbase + F_QKB + it * 8);
        TC_FENCE_AFTER();
        if (it >= 1) MBAR_WAIT0(sbase + F_PVB + (it - 1) * 8);

        // K half-tile it+1 (QK(it) done reading the single K buffer)
        if (it < 31) {
            const float* Kt = Kb + (size_t)(k0 + 64) * DD;
#pragma unroll
            for (int i = 0; i < 2; i++) {
                int lin = tid + i * 512;
                int row = lin >> 4, c4 = (lin & 15) << 2;
                float4 v = *(const float4*)(Kt + (size_t)row * DD + c4);
                split_sts4(sm + F_KH, sm + F_KL, row * 128 + c4 * 2, v);
            }
        }
        // V half-tile it: rows k0..k0+63, transposed [n][k] (PV(it-1) done)
#pragma unroll
        for (int i = 0; i < 2; i++) {
            int lin = tid + i * 512;
            int kr = lin >> 4, n4 = (lin & 15) << 2;
            float4 v = *(const float4*)(Vb + (size_t)(k0 + kr) * DD + n4);
            float vv[4] = {v.x, v.y, v.z, v.w};
#pragma unroll
            for (int j = 0; j < 4; j++) {
                int sw = sw128((n4 + j) * 128 + kr * 2);
                __nv_bfloat16 hh = __float2bfloat16(vv[j]);
                float lo = vv[j] - __bfloat162float(hh);
                *(__nv_bfloat16*)(sm + F_VH + sw) = hh;
                *(__nv_bfloat16*)(sm + F_VL + sw) = __float2bfloat16(lo);
            }
        }
        FENCE_ASYNC();
        __syncthreads();
        if (it < 31 && wid == 0 && elect_one())
            issue_qk(T_S + ((it + 1) & 1) * 64, sbase + F_QKB + (it + 1) * 8);

        // epilogue: S(it) -> exp * inv -> attn (single write) + split into P
        // 4 warp-groups x 16 cols each
        {
            const float iv = invS[myrow];
            uint32_t r[16];
            TC_LD_X16(r, T_S + (it & 1) * 64 + wg * 16);
            TC_WAIT_LD();
            float e[16];
#pragma unroll
            for (int j = 0; j < 16; j++) e[j] = __expf(__uint_as_float(r[j])) * iv;
            float* erow = Eb + (size_t)myrow * LL + k0 + wg * 16;
#pragma unroll
            for (int q = 0; q < 4; q++)
                *(float4*)(erow + q * 4) =
                    make_float4(e[q * 4], e[q * 4 + 1], e[q * 4 + 2], e[q * 4 + 3]);
#pragma unroll
            for (int q = 0; q < 4; q++)
                split_sts4(sm + F_PH, sm + F_PL, myrow * 128 + (wg * 16 + q * 4) * 2,
                           make_float4(e[q * 4], e[q * 4 + 1], e[q * 4 + 2], e[q * 4 + 3]));
        }
        TC_FENCE_BEFORE();
        FENCE_ASYNC();
        __syncthreads();
        if (wid == 0 && elect_one()) issue_pv(it == 0, sbase + F_PVB + it * 8);
    }

    MBAR_WAIT0(sbase + F_PVB + 31 * 8);
    TC_FENCE_AFTER();
    {
        uint32_t r[16];
        TC_LD_X16(r, T_O + wg * 16);
        TC_WAIT_LD();
        TC_FENCE_BEFORE();
        float* orow = Ob + (size_t)myrow * DD + wg * 16;
#pragma unroll
        for (int q = 0; q < 4; q++)
            *(float4*)(orow + q * 4) = make_float4(__uint_as_float(r[q * 4]),
                                                   __uint_as_float(r[q * 4 + 1]),
                                                   __uint_as_float(r[q * 4 + 2]),
                                                   __uint_as_float(r[q * 4 + 3]));
    }
    __syncthreads();
    if (tid == 0) {
#pragma unroll
        for (int i = 0; i < 32; i++) { MBAR_INVAL(sbase + F_QKB + i * 8); MBAR_INVAL(sbase + F_PVB + i * 8); }
    }
    __syncthreads();
    if (wid == 0) { TC_DEALLOC(tbase, 256); }

#else  // scalar fallback
    float* Ts = (float*)sm;
    float q[DD], acc[DD];
    float iv = 0.f;
    if (tid < 128) {
#pragma unroll
        for (int d = 0; d < DD; d++) { q[d] = Qb[(size_t)tid * DD + d]; acc[d] = 0.f; }
        iv = g_inv[bh * LL + tileM + tid];
    }
    float* erow = Eb + (size_t)tid * LL;
    for (int nt = 0; nt < 16; nt++) {
        for (int lin = tid; lin < 128 * 16; lin += blockDim.x) {
            int row = lin >> 4, c4 = (lin & 15) << 2;
            *(float4*)(Ts + row * DD + c4) =
                *(const float4*)(Kb + (size_t)(nt * 128 + row) * DD + c4);
        }
        __syncthreads();
        float p[128];
        if (tid < 128) {
            for (int j = 0; j < 128; j++) {
                float s = 0.f;
#pragma unroll
                for (int d = 0; d < DD; d++) s = fmaf(q[d], Ts[j * DD + d], s);
                p[j] = __expf(s) * iv;
                erow[nt * 128 + j] = p[j];
            }
        }
        __syncthreads();
        for (int lin = tid; lin < 128 * 16; lin += blockDim.x) {
            int row = lin >> 4, c4 = (lin & 15) << 2;
            *(float4*)(Ts + row * DD + c4) =
                *(const float4*)(Vb + (size_t)(nt * 128 + row) * DD + c4);
        }
        __syncthreads();
        if (tid < 128) {
            for (int j = 0; j < 128; j++)
#pragma unroll
                for (int d = 0; d < DD; d++) acc[d] = fmaf(p[j], Ts[j * DD + d], acc[d]);
        }
        __syncthreads();
    }
    if (tid < 128) {
#pragma unroll
        for (int d = 0; d < DD; d += 4)
            *(float4*)(Ob + (size_t)tid * DD + d) =
                make_float4(acc[d], acc[d + 1], acc[d + 2], acc[d + 3]);
    }
#endif
}

// ---------------------------------------------------------------------------
// ctx-only fallback: fused per-row attention (rarely used branch).
// ---------------------------------------------------------------------------
__global__ __launch_bounds__(256) void fused_ctx_kernel(const float* __restrict__ Q,
                                                        const float* __restrict__ K,
                                                        const float* __restrict__ V,
                                                        float* __restrict__ O) {
    __shared__ float q[DD];
    __shared__ float s[LL];
    __shared__ float wred[8];
    __shared__ float bcast;

    const int bh = blockIdx.y;
    const int qi = blockIdx.x;
    const float* Qb = Q + ((size_t)bh * LL + qi) * DD;
    const float* Kb = K + (size_t)bh * LL * DD;
    const float* Vb = V + (size_t)bh * LL * DD;
    float* Ob = O + ((size_t)bh * LL + qi) * DD;

    const int tid = threadIdx.x;
    const int warp = tid >> 5, lane = tid & 31;
    if (tid < DD) q[tid] = Qb[tid];
    __syncthreads();

    float m = -CUDART_INF_F;
    for (int j = tid; j < LL; j += 256) {
        float d = 0.f;
#pragma unroll
        for (int d0 = 0; d0 < DD; d0++) d = fmaf(q[d0], Kb[(size_t)j * DD + d0], d);
        s[j] = d;
        m = fmaxf(m, d);
    }
#pragma unroll
    for (int o = 16; o > 0; o >>= 1) m = fmaxf(m, __shfl_xor_sync(0xffffffffu, m, o));
    if (lane == 0) wred[warp] = m;
    __syncthreads();
    if (warp == 0) {
        float x = (lane < 8) ? wred[lane] : -CUDART_INF_F;
#pragma unroll
        for (int o = 4; o > 0; o >>= 1) x = fmaxf(x, __shfl_xor_sync(0xffffffffu, x, o));
        if (lane == 0) bcast = x;
    }
    __syncthreads();
    m = bcast;

    float ssum = 0.f;
    for (int j = tid; j < LL; j += 256) {
        float e = __expf(s[j] - m);
        s[j] = e;
        ssum += e;
    }
#pragma unroll
    for (int o = 16; o > 0; o >>= 1) ssum += __shfl_xor_sync(0xffffffffu, ssum, o);
    __syncthreads();
    if (lane == 0) wred[warp] = ssum;
    __syncthreads();
    if (warp == 0) {
        float x = (lane < 8) ? wred[lane] : 0.f;
#pragma unroll
        for (int o = 4; o > 0; o >>= 1) x += __shfl_xor_sync(0xffffffffu, x, o);
        if (lane == 0) bcast = 1.f / x;
    }
    __syncthreads();
    const float inv = bcast;

    if (tid < DD) {
        float a = 0.f;
        for (int j = 0; j < LL; j++) a = fmaf(s[j], Vb[(size_t)j * DD + tid], a);
        Ob[tid] = a * inv;
    }
}

// ---------------------------------------------------------------------------
extern "C" void kernel_launch(void* const* d_in, const int* in_sizes, int n_in,
                              void* d_out, int out_size) {
    const float* Q = (const float*)d_in[0];
    const float* K = (const float*)d_in[1];
    const float* V = (const float*)d_in[2];
    float* out = (float*)d_out;

    cudaFuncSetAttribute(qk_rowsum_tc, cudaFuncAttributeMaxDynamicSharedMemorySize, QK_SMEM);
    cudaFuncSetAttribute(fused_pv_tc, cudaFuncAttributeMaxDynamicSharedMemorySize, F_SMEM);

    if ((size_t)out_size >= CTX_ELEMS + ATT_ELEMS) {
        float* ctx = out;
        float* att = out + CTX_ELEMS;
        qk_rowsum_tc<<<dim3(16, BHN), 512, QK_SMEM>>>(Q, K);
        fused_pv_tc<<<dim3(16, BHN), 512, F_SMEM>>>(Q, K, V, att, ctx);
    } else if ((size_t)out_size == ATT_ELEMS) {
        float* scratch = nullptr;
        cudaGetSymbolAddress((void**)&scratch, g_ctx_scratch);
        qk_rowsum_tc<<<dim3(16, BHN), 512, QK_SMEM>>>(Q, K);
        fused_pv_tc<<<dim3(16, BHN), 512, F_SMEM>>>(Q, K, V, out, scratch);
    } else {
        fused_ctx_kernel<<<dim3(LL, BHN), 256>>>(Q, K, V, out);
    }
}

// round 16
// speedup vs baseline: 2.3097x; 1.2146x over previous
#include <cuda_runtime.h>
#include <cuda_bf16.h>
#include <math_constants.h>
#include <cstdint>

// Problem shape: B=4, H=16, L=2048, D=64 (fp32)
#define BHN 64
#define LL  2048
#define DD  64

static const size_t CTX_ELEMS = (size_t)BHN * LL * DD;          // 8,388,608
static const size_t ATT_ELEMS = (size_t)BHN * LL * (size_t)LL;  // 268,435,456

// scratch (static __device__, allowed)
__device__ float g_inv[BHN * LL];                       // per-row 1/rowsum
__device__ float g_ctx_scratch[(size_t)BHN * LL * DD];  // ctx sink for attn-only

#if defined(__CUDA_ARCH_FEAT_SM103_ALL) || defined(__CUDA_ARCH_FEAT_SM100_ALL) || defined(__CUDA_ARCH_FEAT_SM101_ALL)
#define HAS_TC 1
#else
#define HAS_TC 0
#endif

// ===================== SMEM layouts =====================
// K1 (rowsum): [tmem][16 mbars][rowsum 512f][Q hi/lo 32K][Kbuf0 32K][Kbuf1 32K]
#define QK_TMEM 0
#define QK_MBAR 16
#define QK_RS   1024                      /* 512 floats = 2048 B */
#define QK_QH   4096
#define QK_QL   (QK_QH + 16384)
#define QK_KB0  36864
#define QK_KB1  69632
#define QK_SMEM 102400
// K2 (fused recompute+PV):
// [tmem][32 QK bars][32 PV bars][inv 512B] | Qh Ql | Kh Kl | Ph Pl | Vh Vl
#define F_TMEM 0
#define F_QKB  16
#define F_PVB  (F_QKB + 32 * 8)
#define F_INV  (F_PVB + 32 * 8)
#define F_QH   2048
#define F_QL   (F_QH + 16384)
#define F_KH   34816
#define F_KL   (F_KH + 8192)
#define F_PH   51200
#define F_PL   (F_PH + 16384)
#define F_VH   83968
#define F_VL   (F_VH + 8192)
#define F_SMEM 100352

#if HAS_TC
// ===================== PTX helpers =====================
__device__ __forceinline__ uint32_t smem_u32(const void* p) {
    uint32_t a;
    asm("{ .reg .u64 t; cvta.to.shared.u64 t, %1; cvt.u32.u64 %0, t; }" : "=r"(a) : "l"(p));
    return a;
}
__device__ __forceinline__ uint32_t elect_one() {
    uint32_t p;
    asm volatile("{\n\t.reg .pred p;\n\telect.sync _|p, 0xFFFFFFFF;\n\tselp.b32 %0, 1, 0, p;\n\t}" : "=r"(p));
    return p;
}
#define TC_ALLOC(sa, n)  asm volatile("tcgen05.alloc.cta_group::1.sync.aligned.shared::cta.b32 [%0], %1;" :: "r"(sa), "r"(n) : "memory")
#define TC_DEALLOC(t, n) asm volatile("tcgen05.dealloc.cta_group::1.sync.aligned.b32 %0, %1;" :: "r"(t), "r"(n))
#define TC_RELINQ()      asm volatile("tcgen05.relinquish_alloc_permit.cta_group::1.sync.aligned;")
#define TC_COMMIT(mb)    asm volatile("tcgen05.commit.cta_group::1.mbarrier::arrive::one.shared::cluster.b64 [%0];" :: "r"(mb) : "memory")
#define TC_WAIT_LD()     asm volatile("tcgen05.wait::ld.sync.aligned;" ::: "memory")
#define TC_FENCE_AFTER() asm volatile("tcgen05.fence::after_thread_sync;" ::: "memory")
#define TC_FENCE_BEFORE() asm volatile("tcgen05.fence::before_thread_sync;" ::: "memory")
#define FENCE_ASYNC()    asm volatile("fence.proxy.async.shared::cta;" ::: "memory")
#define MBAR_INIT(mb, c) asm volatile("mbarrier.init.shared.b64 [%0], %1;" :: "r"(mb), "r"(c) : "memory")
#define MBAR_INVAL(mb)   asm volatile("mbarrier.inval.shared.b64 [%0];" :: "r"(mb) : "memory")

#define MBAR_WAIT0(mb) do {                                                  \
    uint32_t _mb = (mb); uint32_t _done;                                     \
    asm volatile("{\n\t.reg .pred p;\n\t"                                    \
        "mbarrier.try_wait.parity.acquire.cta.shared::cta.b64 p, [%1], 0;\n\t" \
        "selp.b32 %0, 1, 0, p;\n\t}"                                         \
        : "=r"(_done) : "r"(_mb) : "memory");                                \
    if (!_done) {                                                            \
        asm volatile("{\n\t.reg .pred P1;\n\t"                               \
            "WL_%=:\n\t"                                                     \
            "mbarrier.try_wait.parity.acquire.cta.shared::cta.b64 P1, [%0], 0, 0x989680;\n\t" \
            "@P1 bra.uni WD_%=;\n\t"                                         \
            "bra.uni WL_%=;\n\t"                                             \
            "WD_%=:\n\t}"                                                    \
            :: "r"(_mb) : "memory");                                         \
    }                                                                        \
} while (0)

#define TC_LD_X16(r, ta) \
    asm volatile( \
        "tcgen05.ld.sync.aligned.32x32b.x16.b32 " \
        "{%0, %1, %2, %3, %4, %5, %6, %7, " \
        " %8, %9, %10, %11, %12, %13, %14, %15}, [%16];" \
        : "=r"((r)[0]),  "=r"((r)[1]),  "=r"((r)[2]),  "=r"((r)[3]), \
          "=r"((r)[4]),  "=r"((r)[5]),  "=r"((r)[6]),  "=r"((r)[7]), \
          "=r"((r)[8]),  "=r"((r)[9]),  "=r"((r)[10]), "=r"((r)[11]), \
          "=r"((r)[12]), "=r"((r)[13]), "=r"((r)[14]), "=r"((r)[15]) \
        : "r"(ta))

__device__ __forceinline__ void mma_f16_ss(uint32_t d, uint64_t ad, uint64_t bd,
                                           uint32_t idesc, uint32_t acc) {
    asm volatile(
        "{\n\t.reg .pred p;\n\tsetp.ne.u32 p, %4, 0;\n\t"
        "tcgen05.mma.cta_group::1.kind::f16 [%0], %1, %2, %3, {%5, %5, %5, %5}, p;\n\t}"
        :: "r"(d), "l"(ad), "l"(bd), "r"(idesc), "r"(acc), "r"(0u)
        : "memory");
}

__device__ __forceinline__ uint64_t make_desc(uint32_t addr) {
    return 0x4000404000010000ULL | (uint64_t)((addr >> 4) & 0x3FFF);
}
__device__ __forceinline__ int sw128(int off) { return off ^ ((off >> 3) & 0x70); }

// M=128, N=64 bf16->f32 (proven geometry)
#define IDESC_64 0x8100490u

__device__ __forceinline__ void split_sts4(char* hi_base, char* lo_base, int byte_off, float4 v) {
    int sw = sw128(byte_off);
    __nv_bfloat16 h0 = __float2bfloat16(v.x), h1 = __float2bfloat16(v.y),
                  h2 = __float2bfloat16(v.z), h3 = __float2bfloat16(v.w);
    float l0 = v.x - __bfloat162float(h0), l1 = v.y - __bfloat162float(h1),
          l2 = v.z - __bfloat162float(h2), l3 = v.w - __bfloat162float(h3);
    __nv_bfloat16 g0 = __float2bfloat16(l0), g1 = __float2bfloat16(l1),
                  g2 = __float2bfloat16(l2), g3 = __float2bfloat16(l3);
    uint2 hv, lv;
    hv.x = (uint32_t)__bfloat16_as_ushort(h0) | ((uint32_t)__bfloat16_as_ushort(h1) << 16);
    hv.y = (uint32_t)__bfloat16_as_ushort(h2) | ((uint32_t)__bfloat16_as_ushort(h3) << 16);
    lv.x = (uint32_t)__bfloat16_as_ushort(g0) | ((uint32_t)__bfloat16_as_ushort(g1) << 16);
    lv.y = (uint32_t)__bfloat16_as_ushort(g2) | ((uint32_t)__bfloat16_as_ushort(g3) << 16);
    *(uint2*)(hi_base + sw) = hv;
    *(uint2*)(lo_base + sw) = lv;
}

__device__ __forceinline__ float bf16lo(uint32_t u) {
    return __bfloat162float(__ushort_as_bfloat16((unsigned short)(u & 0xFFFFu)));
}
__device__ __forceinline__ float bf16hi(uint32_t u) {
    return __bfloat162float(__ushort_as_bfloat16((unsigned short)(u >> 16)));
}
#endif  // HAS_TC

// ===================== K1: rowsums of exp(Q K^T) -> g_inv (no E store) ====
// grid (16, 64), 512 threads, 2 CTAs/SM.
__global__ __launch_bounds__(512, 2) __cluster_dims__(1, 1, 1)
void qk_rowsum_tc(const float* __restrict__ Q, const float* __restrict__ K) {
    extern __shared__ char sm[];
    const int tid = threadIdx.x, wid = tid >> 5, lid = tid & 31;
    const int bh = blockIdx.y, tileM = blockIdx.x * 128;
    const float* Qb = Q + ((size_t)bh * LL + tileM) * DD;
    const float* Kb = K + (size_t)bh * LL * DD;

#if HAS_TC
    const uint32_t sbase = smem_u32(sm);
    const int wg = wid >> 2;                 // 0..3 -> cols wg*32..wg*32+31
    const int myrow = (wid & 3) * 32 + lid;

    if (wid == 0) { TC_ALLOC(sbase + QK_TMEM, 256); TC_RELINQ(); }
    if (tid == 0) {
#pragma unroll
        for (int i = 0; i < 16; i++) MBAR_INIT(sbase + QK_MBAR + i * 8, 1);
    }
    __syncthreads();
    uint32_t tbase;
    asm volatile("ld.shared.b32 %0, [%1];" : "=r"(tbase) : "r"(sbase + QK_TMEM));

#pragma unroll
    for (int i = 0; i < 4; i++) {
        int lin = tid + i * 512;
        int row = lin >> 4, c4 = (lin & 15) << 2;
        float4 v = *(const float4*)(Qb + (size_t)row * DD + c4);
        split_sts4(sm + QK_QH, sm + QK_QL, row * 128 + c4 * 2, v);
    }
#pragma unroll
    for (int i = 0; i < 4; i++) {
        int lin = tid + i * 512;
        int row = lin >> 4, c4 = (lin & 15) << 2;
        float4 v = *(const float4*)(Kb + (size_t)row * DD + c4);
        split_sts4(sm + QK_KB0, sm + QK_KB0 + 16384, row * 128 + c4 * 2, v);
    }
    FENCE_ASYNC();
    __syncthreads();

    auto issue_qk = [&](uint32_t kbase, uint32_t dst, uint32_t bar) {
        uint64_t ah = make_desc(sbase + QK_QH), al = make_desc(sbase + QK_QL);
#pragma unroll
        for (int n = 0; n < 2; n++) {
            uint64_t bhd = make_desc(kbase + n * 8192);
            uint64_t bld = make_desc(kbase + 16384 + n * 8192);
            uint32_t d = dst + n * 64;
#pragma unroll
            for (int k = 0; k < 4; k++) mma_f16_ss(d, ah + k * 2, bhd + k * 2, IDESC_64, k > 0);
#pragma unroll
            for (int k = 0; k < 4; k++) mma_f16_ss(d, ah + k * 2, bld + k * 2, IDESC_64, 1);
#pragma unroll
            for (int k = 0; k < 4; k++) mma_f16_ss(d, al + k * 2, bhd + k * 2, IDESC_64, 1);
        }
        TC_COMMIT(bar);
    };

    if (wid == 0 && elect_one()) issue_qk(sbase + QK_KB0, tbase, sbase + QK_MBAR);

    float rs = 0.f;
    for (int nt = 0; nt < 16; nt++) {
        if (nt < 15) {
            const float* Kt = Kb + (size_t)(nt + 1) * 128 * DD;
            uint32_t kb = ((nt + 1) & 1) ? QK_KB1 : QK_KB0;
#pragma unroll
            for (int i = 0; i < 4; i++) {
                int lin = tid + i * 512;
                int row = lin >> 4, c4 = (lin & 15) << 2;
                float4 v = *(const float4*)(Kt + (size_t)row * DD + c4);
                split_sts4(sm + kb, sm + kb + 16384, row * 128 + c4 * 2, v);
            }
            FENCE_ASYNC();
        }
        __syncthreads();
        if (nt < 15 && wid == 0 && elect_one()) {
            uint32_t kb = ((nt + 1) & 1) ? QK_KB1 : QK_KB0;
            issue_qk(sbase + kb, tbase + ((nt + 1) & 1) * 128, sbase + QK_MBAR + (nt + 1) * 8);
        }
        MBAR_WAIT0(sbase + QK_MBAR + nt * 8);
        TC_FENCE_AFTER();

        // 4 warp-groups x 32 cols each (two x16 batches to cap live regs)
#pragma unroll
        for (int h = 0; h < 2; h++) {
            uint32_t r[16];
            TC_LD_X16(r, tbase + (nt & 1) * 128 + wg * 32 + h * 16);
            TC_WAIT_LD();
#pragma unroll
            for (int j = 0; j < 16; j++) rs += __expf(__uint_as_float(r[j]));
        }
        TC_FENCE_BEFORE();
    }

    float* rsbuf = (float*)(sm + QK_RS);
    rsbuf[wg * 128 + myrow] = rs;
    __syncthreads();
    if (wg == 0)
        g_inv[bh * LL + tileM + myrow] =
            1.0f / (rsbuf[myrow] + rsbuf[128 + myrow] + rsbuf[256 + myrow] + rsbuf[384 + myrow]);

    __syncthreads();
    if (tid == 0) {
#pragma unroll
        for (int i = 0; i < 16; i++) MBAR_INVAL(sbase + QK_MBAR + i * 8);
    }
    __syncthreads();
    if (wid == 0) { TC_DEALLOC(tbase, 256); }

#else  // scalar fallback
    float* Ts = (float*)sm;
    float q[DD];
    if (tid < 128) {
#pragma unroll
        for (int d = 0; d < DD; d++) q[d] = Qb[(size_t)tid * DD + d];
    }
    float rs = 0.f;
    for (int nt = 0; nt < 16; nt++) {
        for (int lin = tid; lin < 128 * 16; lin += blockDim.x) {
            int row = lin >> 4, c4 = (lin & 15) << 2;
            *(float4*)(Ts + row * DD + c4) =
                *(const float4*)(Kb + (size_t)(nt * 128 + row) * DD + c4);
        }
        __syncthreads();
        if (tid < 128) {
            for (int j = 0; j < 128; j++) {
                float s = 0.f;
#pragma unroll
                for (int d = 0; d < DD; d++) s = fmaf(q[d], Ts[j * DD + d], s);
                rs += __expf(s);
            }
        }
        __syncthreads();
    }
    if (tid < 128) g_inv[bh * LL + tileM + tid] = 1.0f / rs;
#endif
}

// ========== K2: recompute QK, write normalized attn once, PV accumulate ====
// grid (16, 64), 512 threads, 2 CTAs/SM.
__global__ __launch_bounds__(512, 2) __cluster_dims__(1, 1, 1)
void fused_pv_tc(const float* __restrict__ Q, const float* __restrict__ K,
                 const float* __restrict__ V, float* __restrict__ att,
                 float* __restrict__ ctx) {
    extern __shared__ char sm[];
    const int tid = threadIdx.x, wid = tid >> 5, lid = tid & 31;
    const int bh = blockIdx.y, tileM = blockIdx.x * 128;
    const float* Qb = Q + ((size_t)bh * LL + tileM) * DD;
    const float* Kb = K + (size_t)bh * LL * DD;
    const float* Vb = V + (size_t)bh * LL * DD;
    float* Eb = att + ((size_t)bh * LL + tileM) * LL;
    float* Ob = ctx + ((size_t)bh * LL + tileM) * DD;

#if HAS_TC
    const uint32_t sbase = smem_u32(sm);
    const int wg = wid >> 2;                 // 0..3 -> cols wg*16..wg*16+15
    const int myrow = (wid & 3) * 32 + lid;

    if (wid == 0) { TC_ALLOC(sbase + F_TMEM, 256); TC_RELINQ(); }
    if (tid == 0) {
#pragma unroll
        for (int i = 0; i < 32; i++) { MBAR_INIT(sbase + F_QKB + i * 8, 1); MBAR_INIT(sbase + F_PVB + i * 8, 1); }
    }
    float* invS = (float*)(sm + F_INV);
    if (tid < 128) invS[tid] = g_inv[bh * LL + tileM + tid];
    __syncthreads();
    uint32_t tbase;
    asm volatile("ld.shared.b32 %0, [%1];" : "=r"(tbase) : "r"(sbase + F_TMEM));
    const uint32_t T_S = tbase;          // Sbuf0 @ +0, Sbuf1 @ +64
    const uint32_t T_O = tbase + 128;    // O accumulator, 64 cols

    // resident Q tile
#pragma unroll
    for (int i = 0; i < 4; i++) {
        int lin = tid + i * 512;
        int row = lin >> 4, c4 = (lin & 15) << 2;
        float4 v = *(const float4*)(Qb + (size_t)row * DD + c4);
        split_sts4(sm + F_QH, sm + F_QL, row * 128 + c4 * 2, v);
    }
    // K half-tile 0 (rows 0..63)
#pragma unroll
    for (int i = 0; i < 2; i++) {
        int lin = tid + i * 512;
        int row = lin >> 4, c4 = (lin & 15) << 2;
        float4 v = *(const float4*)(Kb + (size_t)row * DD + c4);
        split_sts4(sm + F_KH, sm + F_KL, row * 128 + c4 * 2, v);
    }
    FENCE_ASYNC();
    __syncthreads();

    auto issue_qk = [&](uint32_t dst, uint32_t bar) {
        uint64_t ah = make_desc(sbase + F_QH), al = make_desc(sbase + F_QL);
        uint64_t bhd = make_desc(sbase + F_KH), bld = make_desc(sbase + F_KL);
#pragma unroll
        for (int k = 0; k < 4; k++) mma_f16_ss(dst, ah + k * 2, bhd + k * 2, IDESC_64, k > 0);
#pragma unroll
        for (int k = 0; k < 4; k++) mma_f16_ss(dst, ah + k * 2, bld + k * 2, IDESC_64, 1);
#pragma unroll
        for (int k = 0; k < 4; k++) mma_f16_ss(dst, al + k * 2, bhd + k * 2, IDESC_64, 1);
        TC_COMMIT(bar);
    };
    auto issue_pv = [&](int first, uint32_t bar) {
        uint64_t ah = make_desc(sbase + F_PH), al = make_desc(sbase + F_PL);
        uint64_t bhd = make_desc(sbase + F_VH), bld = make_desc(sbase + F_VL);
#pragma unroll
        for (int k = 0; k < 4; k++) mma_f16_ss(T_O, ah + k * 2, bhd + k * 2, IDESC_64, !(first && k == 0));
#pragma unroll
        for (int k = 0; k < 4; k++) mma_f16_ss(T_O, ah + k * 2, bld + k * 2, IDESC_64, 1);
#pragma unroll
        for (int k = 0; k < 4; k++) mma_f16_ss(T_O, al + k * 2, bhd + k * 2, IDESC_64, 1);
        TC_COMMIT(bar);
    };

    if (wid == 0 && elect_one()) issue_qk(T_S, sbase + F_QKB);

    for (int it = 0; it < 32; it++) {
        const int k0 = it * 64;
        MBAR_WAIT0(sbase + F_QKB + it * 8);
        TC_FENCE_AFTER();
        if (it >= 1) MBAR_WAIT0(sbase + F_PVB + (it - 1) * 8);

        // K half-tile it+1 (QK(it) done reading the single K buffer)
        if (it < 31) {
            const float* Kt = Kb + (size_t)(k0 + 64) * DD;
#pragma unroll
            for (int i = 0; i < 2; i++) {
                int lin = tid + i * 512;
                int row = lin >> 4, c4 = (lin & 15) << 2;
                float4 v = *(const float4*)(Kt + (size_t)row * DD + c4);
                split_sts4(sm + F_KH, sm + F_KL, row * 128 + c4 * 2, v);
            }
        }
        // V half-tile it: rows k0..k0+63, transposed [n][k] (PV(it-1) done)
#pragma unroll
        for (int i = 0; i < 2; i++) {
            int lin = tid + i * 512;
            int kr = lin >> 4, n4 = (lin & 15) << 2;
            float4 v = *(const float4*)(Vb + (size_t)(k0 + kr) * DD + n4);
            float vv[4] = {v.x, v.y, v.z, v.w};
#pragma unroll
            for (int j = 0; j < 4; j++) {
                int sw = sw128((n4 + j) * 128 + kr * 2);
                __nv_bfloat16 hh = __float2bfloat16(vv[j]);
                float lo = vv[j] - __bfloat162float(hh);
                *(__nv_bfloat16*)(sm + F_VH + sw) = hh;
                *(__nv_bfloat16*)(sm + F_VL + sw) = __float2bfloat16(lo);
            }
        }
        FENCE_ASYNC();
        __syncthreads();
        if (it < 31 && wid == 0 && elect_one())
            issue_qk(T_S + ((it + 1) & 1) * 64, sbase + F_QKB + (it + 1) * 8);

        // epilogue: S(it) -> exp * inv -> split into P smem (no direct gmem store)
        {
            const float iv = invS[myrow];
            uint32_t r[16];
            TC_LD_X16(r, T_S + (it & 1) * 64 + wg * 16);
            TC_WAIT_LD();
            float e[16];
#pragma unroll
            for (int j = 0; j < 16; j++) e[j] = __expf(__uint_as_float(r[j])) * iv;
#pragma unroll
            for (int q = 0; q < 4; q++)
                split_sts4(sm + F_PH, sm + F_PL, myrow * 128 + (wg * 16 + q * 4) * 2,
                           make_float4(e[q * 4], e[q * 4 + 1], e[q * 4 + 2], e[q * 4 + 3]));
        }
        TC_FENCE_BEFORE();
        FENCE_ASYNC();
        __syncthreads();
        if (wid == 0 && elect_one()) issue_pv(it == 0, sbase + F_PVB + it * 8);

        // coalesced attn store (overlaps PV MMA): p = hi + lo from PH/PL smem.
        // 16 consecutive threads cover one 64-float row -> each warp writes 2
        // consecutive rows (4 cache lines per STG.128 instead of 32).
#pragma unroll
        for (int i = 0; i < 4; i++) {
            int lin = tid + i * 512;
            int row = lin >> 4, c4 = (lin & 15) << 2;
            int sw = sw128(row * 128 + c4 * 2);
            uint2 hv = *(uint2*)(sm + F_PH + sw);
            uint2 lv = *(uint2*)(sm + F_PL + sw);
            float4 o;
            o.x = bf16lo(hv.x) + bf16lo(lv.x);
            o.y = bf16hi(hv.x) + bf16hi(lv.x);
            o.z = bf16lo(hv.y) + bf16lo(lv.y);
            o.w = bf16hi(hv.y) + bf16hi(lv.y);
            *(float4*)(Eb + (size_t)row * LL + k0 + c4) = o;
        }
    }

    MBAR_WAIT0(sbase + F_PVB + 31 * 8);
    TC_FENCE_AFTER();
    {
        uint32_t r[16];
        TC_LD_X16(r, T_O + wg * 16);
        TC_WAIT_LD();
        TC_FENCE_BEFORE();
        float* orow = Ob + (size_t)myrow * DD + wg * 16;
#pragma unroll
        for (int q = 0; q < 4; q++)
            *(float4*)(orow + q * 4) = make_float4(__uint_as_float(r[q * 4]),
                                                   __uint_as_float(r[q * 4 + 1]),
                                                   __uint_as_float(r[q * 4 + 2]),
                                                   __uint_as_float(r[q * 4 + 3]));
    }
    __syncthreads();
    if (tid == 0) {
#pragma unroll
        for (int i = 0; i < 32; i++) { MBAR_INVAL(sbase + F_QKB + i * 8); MBAR_INVAL(sbase + F_PVB + i * 8); }
    }
    __syncthreads();
    if (wid == 0) { TC_DEALLOC(tbase, 256); }

#else  // scalar fallback
    float* Ts = (float*)sm;
    float q[DD], acc[DD];
    float iv = 0.f;
    if (tid < 128) {
#pragma unroll
        for (int d = 0; d < DD; d++) { q[d] = Qb[(size_t)tid * DD + d]; acc[d] = 0.f; }
        iv = g_inv[bh * LL + tileM + tid];
    }
    float* erow = Eb + (size_t)tid * LL;
    for (int nt = 0; nt < 16; nt++) {
        for (int lin = tid; lin < 128 * 16; lin += blockDim.x) {
            int row = lin >> 4, c4 = (lin & 15) << 2;
            *(float4*)(Ts + row * DD + c4) =
                *(const float4*)(Kb + (size_t)(nt * 128 + row) * DD + c4);
        }
        __syncthreads();
        float p[128];
        if (tid < 128) {
            for (int j = 0; j < 128; j++) {
                float s = 0.f;
#pragma unroll
                for (int d = 0; d < DD; d++) s = fmaf(q[d], Ts[j * DD + d], s);
                p[j] = __expf(s) * iv;
                erow[nt * 128 + j] = p[j];
            }
        }
        __syncthreads();
        for (int lin = tid; lin < 128 * 16; lin += blockDim.x) {
            int row = lin >> 4, c4 = (lin & 15) << 2;
            *(float4*)(Ts + row * DD + c4) =
                *(const float4*)(Vb + (size_t)(nt * 128 + row) * DD + c4);
        }
        __syncthreads();
        if (tid < 128) {
            for (int j = 0; j < 128; j++)
#pragma unroll
                for (int d = 0; d < DD; d++) acc[d] = fmaf(p[j], Ts[j * DD + d], acc[d]);
        }
        __syncthreads();
    }
    if (tid < 128) {
#pragma unroll
        for (int d = 0; d < DD; d += 4)
            *(float4*)(Ob + (size_t)tid * DD + d) =
                make_float4(acc[d], acc[d + 1], acc[d + 2], acc[d + 3]);
    }
#endif
}

// ---------------------------------------------------------------------------
// ctx-only fallback: fused per-row attention (rarely used branch).
// ---------------------------------------------------------------------------
__global__ __launch_bounds__(256) void fused_ctx_kernel(const float* __restrict__ Q,
                                                        const float* __restrict__ K,
                                                        const float* __restrict__ V,
                                                        float* __restrict__ O) {
    __shared__ float q[DD];
    __shared__ float s[LL];
    __shared__ float wred[8];
    __shared__ float bcast;

    const int bh = blockIdx.y;
    const int qi = blockIdx.x;
    const float* Qb = Q + ((size_t)bh * LL + qi) * DD;
    const float* Kb = K + (size_t)bh * LL * DD;
    const float* Vb = V + (size_t)bh * LL * DD;
    float* Ob = O + ((size_t)bh * LL + qi) * DD;

    const int tid = threadIdx.x;
    const int warp = tid >> 5, lane = tid & 31;
    if (tid < DD) q[tid] = Qb[tid];
    __syncthreads();

    float m = -CUDART_INF_F;
    for (int j = tid; j < LL; j += 256) {
        float d = 0.f;
#pragma unroll
        for (int d0 = 0; d0 < DD; d0++) d = fmaf(q[d0], Kb[(size_t)j * DD + d0], d);
        s[j] = d;
        m = fmaxf(m, d);
    }
#pragma unroll
    for (int o = 16; o > 0; o >>= 1) m = fmaxf(m, __shfl_xor_sync(0xffffffffu, m, o));
    if (lane == 0) wred[warp] = m;
    __syncthreads();
    if (warp == 0) {
        float x = (lane < 8) ? wred[lane] : -CUDART_INF_F;
#pragma unroll
        for (int o = 4; o > 0; o >>= 1) x = fmaxf(x, __shfl_xor_sync(0xffffffffu, x, o));
        if (lane == 0) bcast = x;
    }
    __syncthreads();
    m = bcast;

    float ssum = 0.f;
    for (int j = tid; j < LL; j += 256) {
        float e = __expf(s[j] - m);
        s[j] = e;
        ssum += e;
    }
#pragma unroll
    for (int o = 16; o > 0; o >>= 1) ssum += __shfl_xor_sync(0xffffffffu, ssum, o);
    __syncthreads();
    if (lane == 0) wred[warp] = ssum;
    __syncthreads();
    if (warp == 0) {
        float x = (lane < 8) ? wred[lane] : 0.f;
#pragma unroll
        for (int o = 4; o > 0; o >>= 1) x += __shfl_xor_sync(0xffffffffu, x, o);
        if (lane == 0) bcast = 1.f / x;
    }
    __syncthreads();
    const float inv = bcast;

    if (tid < DD) {
        float a = 0.f;
        for (int j = 0; j < LL; j++) a = fmaf(s[j], Vb[(size_t)j * DD + tid], a);
        Ob[tid] = a * inv;
    }
}

// ---------------------------------------------------------------------------
extern "C" void kernel_launch(void* const* d_in, const int* in_sizes, int n_in,
                              void* d_out, int out_size) {
    const float* Q = (const float*)d_in[0];
    const float* K = (const float*)d_in[1];
    const float* V = (const float*)d_in[2];
    float* out = (float*)d_out;

    cudaFuncSetAttribute(qk_rowsum_tc, cudaFuncAttributeMaxDynamicSharedMemorySize, QK_SMEM);
    cudaFuncSetAttribute(fused_pv_tc, cudaFuncAttributeMaxDynamicSharedMemorySize, F_SMEM);

    if ((size_t)out_size >= CTX_ELEMS + ATT_ELEMS) {
        float* ctx = out;
        float* att = out + CTX_ELEMS;
        qk_rowsum_tc<<<dim3(16, BHN), 512, QK_SMEM>>>(Q, K);
        fused_pv_tc<<<dim3(16, BHN), 512, F_SMEM>>>(Q, K, V, att, ctx);
    } else if ((size_t)out_size == ATT_ELEMS) {
        float* scratch = nullptr;
        cudaGetSymbolAddress((void**)&scratch, g_ctx_scratch);
        qk_rowsum_tc<<<dim3(16, BHN), 512, QK_SMEM>>>(Q, K);
        fused_pv_tc<<<dim3(16, BHN), 512, F_SMEM>>>(Q, K, V, out, scratch);
    } else {
        fused_ctx_kernel<<<dim3(LL, BHN), 256>>>(Q, K, V, out);
    }
}

// round 17
// speedup vs baseline: 2.7872x; 1.2067x over previous
#include <cuda_runtime.h>
#include <cuda_bf16.h>
#include <math_constants.h>
#include <cstdint>

// Problem shape: B=4, H=16, L=2048, D=64 (fp32)
#define BHN 64
#define LL  2048
#define DD  64

static const size_t CTX_ELEMS = (size_t)BHN * LL * DD;          // 8,388,608
static const size_t ATT_ELEMS = (size_t)BHN * LL * (size_t)LL;  // 268,435,456

// scratch (static __device__, allowed)
__device__ float g_inv[BHN * LL];                       // per-row 1/rowsum
__device__ float g_ctx_scratch[(size_t)BHN * LL * DD];  // ctx sink for attn-only

#if defined(__CUDA_ARCH_FEAT_SM103_ALL) || defined(__CUDA_ARCH_FEAT_SM100_ALL) || defined(__CUDA_ARCH_FEAT_SM101_ALL)
#define HAS_TC 1
#else
#define HAS_TC 0
#endif

// ===================== SMEM layouts =====================
// K1 (rowsum): [tmem][16 mbars][rowsum 512f][Q hi/lo 32K][Kbuf0 32K][Kbuf1 32K]
#define QK_TMEM 0
#define QK_MBAR 16
#define QK_RS   1024                      /* 512 floats = 2048 B */
#define QK_QH   4096
#define QK_QL   (QK_QH + 16384)
#define QK_KB0  36864
#define QK_KB1  69632
#define QK_SMEM 102400
// K2 (fused recompute+PV):
// [tmem][32 QK bars][32 PV bars][inv 512B] | Qh Ql | Kh Kl | Ph Pl | Vh Vl
#define F_TMEM 0
#define F_QKB  16
#define F_PVB  (F_QKB + 32 * 8)
#define F_INV  (F_PVB + 32 * 8)
#define F_QH   2048
#define F_QL   (F_QH + 16384)
#define F_KH   34816
#define F_KL   (F_KH + 8192)
#define F_PH   51200
#define F_PL   (F_PH + 16384)
#define F_VH   83968
#define F_VL   (F_VH + 8192)
#define F_SMEM 100352

#if HAS_TC
// ===================== PTX helpers =====================
__device__ __forceinline__ uint32_t smem_u32(const void* p) {
    uint32_t a;
    asm("{ .reg .u64 t; cvta.to.shared.u64 t, %1; cvt.u32.u64 %0, t; }" : "=r"(a) : "l"(p));
    return a;
}
__device__ __forceinline__ uint32_t elect_one() {
    uint32_t p;
    asm volatile("{\n\t.reg .pred p;\n\telect.sync _|p, 0xFFFFFFFF;\n\tselp.b32 %0, 1, 0, p;\n\t}" : "=r"(p));
    return p;
}
#define TC_ALLOC(sa, n)  asm volatile("tcgen05.alloc.cta_group::1.sync.aligned.shared::cta.b32 [%0], %1;" :: "r"(sa), "r"(n) : "memory")
#define TC_DEALLOC(t, n) asm volatile("tcgen05.dealloc.cta_group::1.sync.aligned.b32 %0, %1;" :: "r"(t), "r"(n))
#define TC_RELINQ()      asm volatile("tcgen05.relinquish_alloc_permit.cta_group::1.sync.aligned;")
#define TC_COMMIT(mb)    asm volatile("tcgen05.commit.cta_group::1.mbarrier::arrive::one.shared::cluster.b64 [%0];" :: "r"(mb) : "memory")
#define TC_WAIT_LD()     asm volatile("tcgen05.wait::ld.sync.aligned;" ::: "memory")
#define TC_FENCE_AFTER() asm volatile("tcgen05.fence::after_thread_sync;" ::: "memory")
#define TC_FENCE_BEFORE() asm volatile("tcgen05.fence::before_thread_sync;" ::: "memory")
#define FENCE_ASYNC()    asm volatile("fence.proxy.async.shared::cta;" ::: "memory")
#define MBAR_INIT(mb, c) asm volatile("mbarrier.init.shared.b64 [%0], %1;" :: "r"(mb), "r"(c) : "memory")
#define MBAR_INVAL(mb)   asm volatile("mbarrier.inval.shared.b64 [%0];" :: "r"(mb) : "memory")

#define MBAR_WAIT0(mb) do {                                                  \
    uint32_t _mb = (mb); uint32_t _done;                                     \
    asm volatile("{\n\t.reg .pred p;\n\t"                                    \
        "mbarrier.try_wait.parity.acquire.cta.shared::cta.b64 p, [%1], 0;\n\t" \
        "selp.b32 %0, 1, 0, p;\n\t}"                                         \
        : "=r"(_done) : "r"(_mb) : "memory");                                \
    if (!_done) {                                                            \
        asm volatile("{\n\t.reg .pred P1;\n\t"                               \
            "WL_%=:\n\t"                                                     \
            "mbarrier.try_wait.parity.acquire.cta.shared::cta.b64 P1, [%0], 0, 0x989680;\n\t" \
            "@P1 bra.uni WD_%=;\n\t"                                         \
            "bra.uni WL_%=;\n\t"                                             \
            "WD_%=:\n\t}"                                                    \
            :: "r"(_mb) : "memory");                                         \
    }                                                                        \
} while (0)

#define TC_LD_X16(r, ta) \
    asm volatile( \
        "tcgen05.ld.sync.aligned.32x32b.x16.b32 " \
        "{%0, %1, %2, %3, %4, %5, %6, %7, " \
        " %8, %9, %10, %11, %12, %13, %14, %15}, [%16];" \
        : "=r"((r)[0]),  "=r"((r)[1]),  "=r"((r)[2]),  "=r"((r)[3]), \
          "=r"((r)[4]),  "=r"((r)[5]),  "=r"((r)[6]),  "=r"((r)[7]), \
          "=r"((r)[8]),  "=r"((r)[9]),  "=r"((r)[10]), "=r"((r)[11]), \
          "=r"((r)[12]), "=r"((r)[13]), "=r"((r)[14]), "=r"((r)[15]) \
        : "r"(ta))

__device__ __forceinline__ void mma_f16_ss(uint32_t d, uint64_t ad, uint64_t bd,
                                           uint32_t idesc, uint32_t acc) {
    asm volatile(
        "{\n\t.reg .pred p;\n\tsetp.ne.u32 p, %4, 0;\n\t"
        "tcgen05.mma.cta_group::1.kind::f16 [%0], %1, %2, %3, {%5, %5, %5, %5}, p;\n\t}"
        :: "r"(d), "l"(ad), "l"(bd), "r"(idesc), "r"(acc), "r"(0u)
        : "memory");
}

__device__ __forceinline__ uint64_t make_desc(uint32_t addr) {
    return 0x4000404000010000ULL | (uint64_t)((addr >> 4) & 0x3FFF);
}
__device__ __forceinline__ int sw128(int off) { return off ^ ((off >> 3) & 0x70); }

// M=128, N=64 bf16->f32 (proven geometry)
#define IDESC_64 0x8100490u

__device__ __forceinline__ void split_sts4(char* hi_base, char* lo_base, int byte_off, float4 v) {
    int sw = sw128(byte_off);
    __nv_bfloat16 h0 = __float2bfloat16(v.x), h1 = __float2bfloat16(v.y),
                  h2 = __float2bfloat16(v.z), h3 = __float2bfloat16(v.w);
    float l0 = v.x - __bfloat162float(h0), l1 = v.y - __bfloat162float(h1),
          l2 = v.z - __bfloat162float(h2), l3 = v.w - __bfloat162float(h3);
    __nv_bfloat16 g0 = __float2bfloat16(l0), g1 = __float2bfloat16(l1),
                  g2 = __float2bfloat16(l2), g3 = __float2bfloat16(l3);
    uint2 hv, lv;
    hv.x = (uint32_t)__bfloat16_as_ushort(h0) | ((uint32_t)__bfloat16_as_ushort(h1) << 16);
    hv.y = (uint32_t)__bfloat16_as_ushort(h2) | ((uint32_t)__bfloat16_as_ushort(h3) << 16);
    lv.x = (uint32_t)__bfloat16_as_ushort(g0) | ((uint32_t)__bfloat16_as_ushort(g1) << 16);
    lv.y = (uint32_t)__bfloat16_as_ushort(g2) | ((uint32_t)__bfloat16_as_ushort(g3) << 16);
    *(uint2*)(hi_base + sw) = hv;
    *(uint2*)(lo_base + sw) = lv;
}

__device__ __forceinline__ float bf16lo(uint32_t u) {
    return __bfloat162float(__ushort_as_bfloat16((unsigned short)(u & 0xFFFFu)));
}
__device__ __forceinline__ float bf16hi(uint32_t u) {
    return __bfloat162float(__ushort_as_bfloat16((unsigned short)(u >> 16)));
}
#endif  // HAS_TC

// ===================== K1: rowsums of exp(Q K^T) -> g_inv (no E store) ====
// grid (16, 64), 512 threads, 2 CTAs/SM.
__global__ __launch_bounds__(512, 2) __cluster_dims__(1, 1, 1)
void qk_rowsum_tc(const float* __restrict__ Q, const float* __restrict__ K) {
    extern __shared__ char sm[];
    const int tid = threadIdx.x, wid = tid >> 5, lid = tid & 31;
    const int bh = blockIdx.y, tileM = blockIdx.x * 128;
    const float* Qb = Q + ((size_t)bh * LL + tileM) * DD;
    const float* Kb = K + (size_t)bh * LL * DD;

#if HAS_TC
    const uint32_t sbase = smem_u32(sm);
    const int wg = wid >> 2;                 // 0..3 -> cols wg*32..wg*32+31
    const int myrow = (wid & 3) * 32 + lid;

    if (wid == 0) { TC_ALLOC(sbase + QK_TMEM, 256); TC_RELINQ(); }
    if (tid == 0) {
#pragma unroll
        for (int i = 0; i < 16; i++) MBAR_INIT(sbase + QK_MBAR + i * 8, 1);
    }
    __syncthreads();
    uint32_t tbase;
    asm volatile("ld.shared.b32 %0, [%1];" : "=r"(tbase) : "r"(sbase + QK_TMEM));

#pragma unroll
    for (int i = 0; i < 4; i++) {
        int lin = tid + i * 512;
        int row = lin >> 4, c4 = (lin & 15) << 2;
        float4 v = *(const float4*)(Qb + (size_t)row * DD + c4);
        split_sts4(sm + QK_QH, sm + QK_QL, row * 128 + c4 * 2, v);
    }
#pragma unroll
    for (int i = 0; i < 4; i++) {
        int lin = tid + i * 512;
        int row = lin >> 4, c4 = (lin & 15) << 2;
        float4 v = *(const float4*)(Kb + (size_t)row * DD + c4);
        split_sts4(sm + QK_KB0, sm + QK_KB0 + 16384, row * 128 + c4 * 2, v);
    }
    FENCE_ASYNC();
    __syncthreads();

    auto issue_qk = [&](uint32_t kbase, uint32_t dst, uint32_t bar) {
        uint64_t ah = make_desc(sbase + QK_QH), al = make_desc(sbase + QK_QL);
#pragma unroll
        for (int n = 0; n < 2; n++) {
            uint64_t bhd = make_desc(kbase + n * 8192);
            uint64_t bld = make_desc(kbase + 16384 + n * 8192);
            uint32_t d = dst + n * 64;
#pragma unroll
            for (int k = 0; k < 4; k++) mma_f16_ss(d, ah + k * 2, bhd + k * 2, IDESC_64, k > 0);
#pragma unroll
            for (int k = 0; k < 4; k++) mma_f16_ss(d, ah + k * 2, bld + k * 2, IDESC_64, 1);
#pragma unroll
            for (int k = 0; k < 4; k++) mma_f16_ss(d, al + k * 2, bhd + k * 2, IDESC_64, 1);
        }
        TC_COMMIT(bar);
    };

    if (wid == 0 && elect_one()) issue_qk(sbase + QK_KB0, tbase, sbase + QK_MBAR);

    float rs = 0.f;
    for (int nt = 0; nt < 16; nt++) {
        if (nt < 15) {
            const float* Kt = Kb + (size_t)(nt + 1) * 128 * DD;
            uint32_t kb = ((nt + 1) & 1) ? QK_KB1 : QK_KB0;
#pragma unroll
            for (int i = 0; i < 4; i++) {
                int lin = tid + i * 512;
                int row = lin >> 4, c4 = (lin & 15) << 2;
                float4 v = *(const float4*)(Kt + (size_t)row * DD + c4);
                split_sts4(sm + kb, sm + kb + 16384, row * 128 + c4 * 2, v);
            }
            FENCE_ASYNC();
        }
        __syncthreads();
        if (nt < 15 && wid == 0 && elect_one()) {
            uint32_t kb = ((nt + 1) & 1) ? QK_KB1 : QK_KB0;
            issue_qk(sbase + kb, tbase + ((nt + 1) & 1) * 128, sbase + QK_MBAR + (nt + 1) * 8);
        }
        MBAR_WAIT0(sbase + QK_MBAR + nt * 8);
        TC_FENCE_AFTER();

        // 4 warp-groups x 32 cols each (two x16 batches to cap live regs)
#pragma unroll
        for (int h = 0; h < 2; h++) {
            uint32_t r[16];
            TC_LD_X16(r, tbase + (nt & 1) * 128 + wg * 32 + h * 16);
            TC_WAIT_LD();
#pragma unroll
            for (int j = 0; j < 16; j++) rs += __expf(__uint_as_float(r[j]));
        }
        TC_FENCE_BEFORE();
    }

    float* rsbuf = (float*)(sm + QK_RS);
    rsbuf[wg * 128 + myrow] = rs;
    __syncthreads();
    if (wg == 0)
        g_inv[bh * LL + tileM + myrow] =
            1.0f / (rsbuf[myrow] + rsbuf[128 + myrow] + rsbuf[256 + myrow] + rsbuf[384 + myrow]);

    __syncthreads();
    if (tid == 0) {
#pragma unroll
        for (int i = 0; i < 16; i++) MBAR_INVAL(sbase + QK_MBAR + i * 8);
    }
    __syncthreads();
    if (wid == 0) { TC_DEALLOC(tbase, 256); }

#else  // scalar fallback
    float* Ts = (float*)sm;
    float q[DD];
    if (tid < 128) {
#pragma unroll
        for (int d = 0; d < DD; d++) q[d] = Qb[(size_t)tid * DD + d];
    }
    float rs = 0.f;
    for (int nt = 0; nt < 16; nt++) {
        for (int lin = tid; lin < 128 * 16; lin += blockDim.x) {
            int row = lin >> 4, c4 = (lin & 15) << 2;
            *(float4*)(Ts + row * DD + c4) =
                *(const float4*)(Kb + (size_t)(nt * 128 + row) * DD + c4);
        }
        __syncthreads();
        if (tid < 128) {
            for (int j = 0; j < 128; j++) {
                float s = 0.f;
#pragma unroll
                for (int d = 0; d < DD; d++) s = fmaf(q[d], Ts[j * DD + d], s);
                rs += __expf(s);
            }
        }
        __syncthreads();
    }
    if (tid < 128) g_inv[bh * LL + tileM + tid] = 1.0f / rs;
#endif
}

// ========== K2: recompute QK, write normalized attn once, PV accumulate ====
// grid (16, 64), 512 threads, 2 CTAs/SM.
__global__ __launch_bounds__(512, 2) __cluster_dims__(1, 1, 1)
void fused_pv_tc(const float* __restrict__ Q, const float* __restrict__ K,
                 const float* __restrict__ V, float* __restrict__ att,
                 float* __restrict__ ctx) {
    extern __shared__ char sm[];
    const int tid = threadIdx.x, wid = tid >> 5, lid = tid & 31;
    const int bh = blockIdx.y, tileM = blockIdx.x * 128;
    const float* Qb = Q + ((size_t)bh * LL + tileM) * DD;
    const float* Kb = K + (size_t)bh * LL * DD;
    const float* Vb = V + (size_t)bh * LL * DD;
    float* Eb = att + ((size_t)bh * LL + tileM) * LL;
    float* Ob = ctx + ((size_t)bh * LL + tileM) * DD;

#if HAS_TC
    const uint32_t sbase = smem_u32(sm);
    const int wg = wid >> 2;                 // 0..3 -> cols wg*16..wg*16+15
    const int myrow = (wid & 3) * 32 + lid;

    if (wid == 0) { TC_ALLOC(sbase + F_TMEM, 256); TC_RELINQ(); }
    if (tid == 0) {
#pragma unroll
        for (int i = 0; i < 32; i++) { MBAR_INIT(sbase + F_QKB + i * 8, 1); MBAR_INIT(sbase + F_PVB + i * 8, 1); }
    }
    float* invS = (float*)(sm + F_INV);
    if (tid < 128) invS[tid] = g_inv[bh * LL + tileM + tid];
    __syncthreads();
    uint32_t tbase;
    asm volatile("ld.shared.b32 %0, [%1];" : "=r"(tbase) : "r"(sbase + F_TMEM));
    const uint32_t T_S = tbase;          // Sbuf0 @ +0, Sbuf1 @ +64
    const uint32_t T_O = tbase + 128;    // O accumulator, 64 cols

    // resident Q tile
#pragma unroll
    for (int i = 0; i < 4; i++) {
        int lin = tid + i * 512;
        int row = lin >> 4, c4 = (lin & 15) << 2;
        float4 v = *(const float4*)(Qb + (size_t)row * DD + c4);
        split_sts4(sm + F_QH, sm + F_QL, row * 128 + c4 * 2, v);
    }
    // K half-tile 0 (rows 0..63)
#pragma unroll
    for (int i = 0; i < 2; i++) {
        int lin = tid + i * 512;
        int row = lin >> 4, c4 = (lin & 15) << 2;
        float4 v = *(const float4*)(Kb + (size_t)row * DD + c4);
        split_sts4(sm + F_KH, sm + F_KL, row * 128 + c4 * 2, v);
    }
    FENCE_ASYNC();
    __syncthreads();

    auto issue_qk = [&](uint32_t dst, uint32_t bar) {
        uint64_t ah = make_desc(sbase + F_QH), al = make_desc(sbase + F_QL);
        uint64_t bhd = make_desc(sbase + F_KH), bld = make_desc(sbase + F_KL);
#pragma unroll
        for (int k = 0; k < 4; k++) mma_f16_ss(dst, ah + k * 2, bhd + k * 2, IDESC_64, k > 0);
#pragma unroll
        for (int k = 0; k < 4; k++) mma_f16_ss(dst, ah + k * 2, bld + k * 2, IDESC_64, 1);
#pragma unroll
        for (int k = 0; k < 4; k++) mma_f16_ss(dst, al + k * 2, bhd + k * 2, IDESC_64, 1);
        TC_COMMIT(bar);
    };
    auto issue_pv = [&](int first, uint32_t bar) {
        uint64_t ah = make_desc(sbase + F_PH), al = make_desc(sbase + F_PL);
        uint64_t bhd = make_desc(sbase + F_VH), bld = make_desc(sbase + F_VL);
#pragma unroll
        for (int k = 0; k < 4; k++) mma_f16_ss(T_O, ah + k * 2, bhd + k * 2, IDESC_64, !(first && k == 0));
#pragma unroll
        for (int k = 0; k < 4; k++) mma_f16_ss(T_O, ah + k * 2, bld + k * 2, IDESC_64, 1);
#pragma unroll
        for (int k = 0; k < 4; k++) mma_f16_ss(T_O, al + k * 2, bhd + k * 2, IDESC_64, 1);
        TC_COMMIT(bar);
    };

    if (wid == 0 && elect_one()) issue_qk(T_S, sbase + F_QKB);

    for (int it = 0; it < 32; it++) {
        const int k0 = it * 64;
        MBAR_WAIT0(sbase + F_QKB + it * 8);
        TC_FENCE_AFTER();
        if (it >= 1) MBAR_WAIT0(sbase + F_PVB + (it - 1) * 8);

        // K half-tile it+1 (QK(it) done reading the single K buffer)
        if (it < 31) {
            const float* Kt = Kb + (size_t)(k0 + 64) * DD;
#pragma unroll
            for (int i = 0; i < 2; i++) {
                int lin = tid + i * 512;
                int row = lin >> 4, c4 = (lin & 15) << 2;
                float4 v = *(const float4*)(Kt + (size_t)row * DD + c4);
                split_sts4(sm + F_KH, sm + F_KL, row * 128 + c4 * 2, v);
            }
        }
        // V half-tile it: 64 k-rows x 64 n -> [n][k] split, conflict-aware.
        // thread -> (n = tid&63, kc = tid>>6): 8 k-strided coalesced LDG.32,
        // one 16B STS per buffer at sw128(n*128 + kc*16); lane-consecutive n
        // spreads swizzle phases across all 8 16B columns (minimum wavefronts).
        {
            const int n = tid & 63, kc = tid >> 6;
            const int kk = kc * 8;
            uint32_t h[8], l[8];
#pragma unroll
            for (int j = 0; j < 8; j++) {
                float v = Vb[(size_t)(k0 + kk + j) * DD + n];
                __nv_bfloat16 hh = __float2bfloat16(v);
                float lo = v - __bfloat162float(hh);
                h[j] = (uint32_t)__bfloat16_as_ushort(hh);
                l[j] = (uint32_t)__bfloat16_as_ushort(__float2bfloat16(lo));
            }
            uint4 hv, lv;
            hv.x = h[0] | (h[1] << 16); hv.y = h[2] | (h[3] << 16);
            hv.z = h[4] | (h[5] << 16); hv.w = h[6] | (h[7] << 16);
            lv.x = l[0] | (l[1] << 16); lv.y = l[2] | (l[3] << 16);
            lv.z = l[4] | (l[5] << 16); lv.w = l[6] | (l[7] << 16);
            int sw = sw128(n * 128 + kk * 2);
            *(uint4*)(sm + F_VH + sw) = hv;
            *(uint4*)(sm + F_VL + sw) = lv;
        }
        FENCE_ASYNC();
        __syncthreads();
        if (it < 31 && wid == 0 && elect_one())
            issue_qk(T_S + ((it + 1) & 1) * 64, sbase + F_QKB + (it + 1) * 8);

        // epilogue: S(it) -> exp * inv -> split into P smem (no direct gmem store)
        {
            const float iv = invS[myrow];
            uint32_t r[16];
            TC_LD_X16(r, T_S + (it & 1) * 64 + wg * 16);
            TC_WAIT_LD();
            float e[16];
#pragma unroll
            for (int j = 0; j < 16; j++) e[j] = __expf(__uint_as_float(r[j])) * iv;
#pragma unroll
            for (int q = 0; q < 4; q++)
                split_sts4(sm + F_PH, sm + F_PL, myrow * 128 + (wg * 16 + q * 4) * 2,
                           make_float4(e[q * 4], e[q * 4 + 1], e[q * 4 + 2], e[q * 4 + 3]));
        }
        TC_FENCE_BEFORE();
        FENCE_ASYNC();
        __syncthreads();
        if (wid == 0 && elect_one()) issue_pv(it == 0, sbase + F_PVB + it * 8);

        // coalesced attn store (overlaps PV MMA): p = hi + lo from PH/PL smem.
#pragma unroll
        for (int i = 0; i < 4; i++) {
            int lin = tid + i * 512;
            int row = lin >> 4, c4 = (lin & 15) << 2;
            int sw = sw128(row * 128 + c4 * 2);
            uint2 hv = *(uint2*)(sm + F_PH + sw);
            uint2 lv = *(uint2*)(sm + F_PL + sw);
            float4 o;
            o.x = bf16lo(hv.x) + bf16lo(lv.x);
            o.y = bf16hi(hv.x) + bf16hi(lv.x);
            o.z = bf16lo(hv.y) + bf16lo(lv.y);
            o.w = bf16hi(hv.y) + bf16hi(lv.y);
            *(float4*)(Eb + (size_t)row * LL + k0 + c4) = o;
        }
    }

    MBAR_WAIT0(sbase + F_PVB + 31 * 8);
    TC_FENCE_AFTER();
    {
        uint32_t r[16];
        TC_LD_X16(r, T_O + wg * 16);
        TC_WAIT_LD();
        TC_FENCE_BEFORE();
        float* orow = Ob + (size_t)myrow * DD + wg * 16;
#pragma unroll
        for (int q = 0; q < 4; q++)
            *(float4*)(orow + q * 4) = make_float4(__uint_as_float(r[q * 4]),
                                                   __uint_as_float(r[q * 4 + 1]),
                                                   __uint_as_float(r[q * 4 + 2]),
                                                   __uint_as_float(r[q * 4 + 3]));
    }
    __syncthreads();
    if (tid == 0) {
#pragma unroll
        for (int i = 0; i < 32; i++) { MBAR_INVAL(sbase + F_QKB + i * 8); MBAR_INVAL(sbase + F_PVB + i * 8); }
    }
    __syncthreads();
    if (wid == 0) { TC_DEALLOC(tbase, 256); }

#else  // scalar fallback
    float* Ts = (float*)sm;
    float q[DD], acc[DD];
    float iv = 0.f;
    if (tid < 128) {
#pragma unroll
        for (int d = 0; d < DD; d++) { q[d] = Qb[(size_t)tid * DD + d]; acc[d] = 0.f; }
        iv = g_inv[bh * LL + tileM + tid];
    }
    float* erow = Eb + (size_t)tid * LL;
    for (int nt = 0; nt < 16; nt++) {
        for (int lin = tid; lin < 128 * 16; lin += blockDim.x) {
            int row = lin >> 4, c4 = (lin & 15) << 2;
            *(float4*)(Ts + row * DD + c4) =
                *(const float4*)(Kb + (size_t)(nt * 128 + row) * DD + c4);
        }
        __syncthreads();
        float p[128];
        if (tid < 128) {
            for (int j = 0; j < 128; j++) {
                float s = 0.f;
#pragma unroll
                for (int d = 0; d < DD; d++) s = fmaf(q[d], Ts[j * DD + d], s);
                p[j] = __expf(s) * iv;
                erow[nt * 128 + j] = p[j];
            }
        }
        __syncthreads();
        for (int lin = tid; lin < 128 * 16; lin += blockDim.x) {
            int row = lin >> 4, c4 = (lin & 15) << 2;
            *(float4*)(Ts + row * DD + c4) =
                *(const float4*)(Vb + (size_t)(nt * 128 + row) * DD + c4);
        }
        __syncthreads();
        if (tid < 128) {
            for (int j = 0; j < 128; j++)
#pragma unroll
                for (int d = 0; d < DD; d++) acc[d] = fmaf(p[j], Ts[j * DD + d], acc[d]);
        }
        __syncthreads();
    }
    if (tid < 128) {
#pragma unroll
        for (int d = 0; d < DD; d += 4)
            *(float4*)(Ob + (size_t)tid * DD + d) =
                make_float4(acc[d], acc[d + 1], acc[d + 2], acc[d + 3]);
    }
#endif
}

// ---------------------------------------------------------------------------
// ctx-only fallback: fused per-row attention (rarely used branch).
// ---------------------------------------------------------------------------
__global__ __launch_bounds__(256) void fused_ctx_kernel(const float* __restrict__ Q,
                                                        const float* __restrict__ K,
                                                        const float* __restrict__ V,
                                                        float* __restrict__ O) {
    __shared__ float q[DD];
    __shared__ float s[LL];
    __shared__ float wred[8];
    __shared__ float bcast;

    const int bh = blockIdx.y;
    const int qi = blockIdx.x;
    const float* Qb = Q + ((size_t)bh * LL + qi) * DD;
    const float* Kb = K + (size_t)bh * LL * DD;
    const float* Vb = V + (size_t)bh * LL * DD;
    float* Ob = O + ((size_t)bh * LL + qi) * DD;

    const int tid = threadIdx.x;
    const int warp = tid >> 5, lane = tid & 31;
    if (tid < DD) q[tid] = Qb[tid];
    __syncthreads();

    float m = -CUDART_INF_F;
    for (int j = tid; j < LL; j += 256) {
        float d = 0.f;
#pragma unroll
        for (int d0 = 0; d0 < DD; d0++) d = fmaf(q[d0], Kb[(size_t)j * DD + d0], d);
        s[j] = d;
        m = fmaxf(m, d);
    }
#pragma unroll
    for (int o = 16; o > 0; o >>= 1) m = fmaxf(m, __shfl_xor_sync(0xffffffffu, m, o));
    if (lane == 0) wred[warp] = m;
    __syncthreads();
    if (warp == 0) {
        float x = (lane < 8) ? wred[lane] : -CUDART_INF_F;
#pragma unroll
        for (int o = 4; o > 0; o >>= 1) x = fmaxf(x, __shfl_xor_sync(0xffffffffu, x, o));
        if (lane == 0) bcast = x;
    }
    __syncthreads();
    m = bcast;

    float ssum = 0.f;
    for (int j = tid; j < LL; j += 256) {
        float e = __expf(s[j] - m);
        s[j] = e;
        ssum += e;
    }
#pragma unroll
    for (int o = 16; o > 0; o >>= 1) ssum += __shfl_xor_sync(0xffffffffu, ssum, o);
    __syncthreads();
    if (lane == 0) wred[warp] = ssum;
    __syncthreads();
    if (warp == 0) {
        float x = (lane < 8) ? wred[lane] : 0.f;
#pragma unroll
        for (int o = 4; o > 0; o >>= 1) x += __shfl_xor_sync(0xffffffffu, x, o);
        if (lane == 0) bcast = 1.f / x;
    }
    __syncthreads();
    const float inv = bcast;

    if (tid < DD) {
        float a = 0.f;
        for (int j = 0; j < LL; j++) a = fmaf(s[j], Vb[(size_t)j * DD + tid], a);
        Ob[tid] = a * inv;
    }
}

// ---------------------------------------------------------------------------
extern "C" void kernel_launch(void* const* d_in, const int* in_sizes, int n_in,
                              void* d_out, int out_size) {
    const float* Q = (const float*)d_in[0];
    const float* K = (const float*)d_in[1];
    const float* V = (const float*)d_in[2];
    float* out = (float*)d_out;

    cudaFuncSetAttribute(qk_rowsum_tc, cudaFuncAttributeMaxDynamicSharedMemorySize, QK_SMEM);
    cudaFuncSetAttribute(fused_pv_tc, cudaFuncAttributeMaxDynamicSharedMemorySize, F_SMEM);

    if ((size_t)out_size >= CTX_ELEMS + ATT_ELEMS) {
        float* ctx = out;
        float* att = out + CTX_ELEMS;
        qk_rowsum_tc<<<dim3(16, BHN), 512, QK_SMEM>>>(Q, K);
        fused_pv_tc<<<dim3(16, BHN), 512, F_SMEM>>>(Q, K, V, att, ctx);
    } else if ((size_t)out_size == ATT_ELEMS) {
        float* scratch = nullptr;
        cudaGetSymbolAddress((void**)&scratch, g_ctx_scratch);
        qk_rowsum_tc<<<dim3(16, BHN), 512, QK_SMEM>>>(Q, K);
        fused_pv_tc<<<dim3(16, BHN), 512, F_SMEM>>>(Q, K, V, out, scratch);
    } else {
        fused_ctx_kernel<<<dim3(LL, BHN), 256>>>(Q, K, V, out);
    }
}